// round 11
// baseline (speedup 1.0000x reference)
#include <cuda_runtime.h>
#include <cstdint>
#include <cstddef>

#define SEQ     4096
#define DMODEL  2048
#define DH      128
#define CHUNK   256          // keys per split-KV work unit
#define MAXC    16           // max chunks per q-tile (4096/256)

// Scratch (allocation-free rule: __device__ globals)
__device__ float g_Q[SEQ * DH];
__device__ float g_K[SEQ * DH];
__device__ float g_V[SEQ * DH];
// W pre-converted to tf32, fragment-pair order: [3][256 kb][128 n][4 t4][2]
__device__ float g_Wf[3 * 256 * 128 * 8];
// split-KV partials: [64 q-tiles][16 chunks][64 rows][128 cols]
__device__ float g_Opart[64 * MAXC * 64 * DH];
__device__ float g_mpart[64 * MAXC * 64];
__device__ float g_lpart[64 * MAXC * 64];

__device__ __forceinline__ uint32_t f2tf(float x) {
    uint32_t r;
    asm("cvt.rna.tf32.f32 %0, %1;" : "=r"(r) : "f"(x));
    return r;
}
__device__ __forceinline__ float ex2(float x) {
    float y;
    asm("ex2.approx.ftz.f32 %0, %1;" : "=f"(y) : "f"(x));
    return y;
}
__device__ __forceinline__ void mma_tf32(float d[4], const uint32_t a[4],
                                         uint32_t b0, uint32_t b1) {
    asm volatile(
        "mma.sync.aligned.m16n8k8.row.col.f32.tf32.tf32.f32 "
        "{%0,%1,%2,%3},{%4,%5,%6,%7},{%8,%9},{%0,%1,%2,%3};\n"
        : "+f"(d[0]), "+f"(d[1]), "+f"(d[2]), "+f"(d[3])
        : "r"(a[0]), "r"(a[1]), "r"(a[2]), "r"(a[3]), "r"(b0), "r"(b1));
}
__device__ __forceinline__ void cpa16(uint32_t dst, const void* src) {
    asm volatile("cp.async.cg.shared.global [%0], [%1], 16;\n" :: "r"(dst), "l"(src));
}
__device__ __forceinline__ void cp_commit() {
    asm volatile("cp.async.commit_group;\n" ::);
}
template <int N>
__device__ __forceinline__ void cp_wait() {
    asm volatile("cp.async.wait_group %0;\n" :: "n"(N));
}
__device__ __forceinline__ uint32_t s2u(const void* p) {
    return (uint32_t)__cvta_generic_to_shared(p);
}

// ---------------------------------------------------------------------------
// prep_w: round W to tf32 and reorder into MMA b-fragment pairs:
// g_Wf[mat][kb][n][t4][2] = { W[n][8kb+t4], W[n][8kb+t4+4] }
// ---------------------------------------------------------------------------
__global__ __launch_bounds__(256)
void prep_w(const float* __restrict__ wq, const float* __restrict__ wk,
            const float* __restrict__ wv) {
    int id = blockIdx.x * 256 + threadIdx.x;       // 0 .. 393215
    int mat = id >> 17;
    int rem = id & 131071;
    int kb = rem >> 9;
    int rem2 = rem & 511;
    int n = rem2 >> 2;
    int t4 = rem2 & 3;
    const float* W = (mat == 0) ? wq : (mat == 1) ? wk : wv;
    float a = W[(size_t)n * DMODEL + kb * 8 + t4];
    float b = W[(size_t)n * DMODEL + kb * 8 + t4 + 4];
    float2 o;
    o.x = __uint_as_float(f2tf(a));
    o.y = __uint_as_float(f2tf(b));
    *(float2*)&g_Wf[(((size_t)mat * 256 + kb) * 128 + n) * 8 + t4 * 2] = o;
}

// ---------------------------------------------------------------------------
// Projection v4 (unchanged from the 127.6 build): 64x128 tile, grid (64,3),
// 3-stage cp.async pipeline, pre-tf32 W fragment pairs.
// ---------------------------------------------------------------------------
#define PJ_DEPTH 3
#define XSTR     36   // bank = (4g + t4) % 32, conflict-free
#define XS_FL    (64 * XSTR)
#define WF_FL    (4 * 128 * 8)
#define PJ_SMEM  (PJ_DEPTH * (XS_FL + WF_FL) * 4)   // 76800 B

__global__ __launch_bounds__(256, 2)
void proj_kernel(const float* __restrict__ xq, const float* __restrict__ xk,
                 const float* __restrict__ xv,
                 const float* __restrict__ bq, const float* __restrict__ bk,
                 const float* __restrict__ bv) {
    extern __shared__ float sm[];
    float* Xs  = sm;                          // [3][64][36]
    float* WfS = sm + PJ_DEPTH * XS_FL;       // [3][4][128][8]

    const float* X; const float* bias; float* out; int mat;
    if (blockIdx.y == 0)      { X = xq; bias = bq; out = g_Q; mat = 0; }
    else if (blockIdx.y == 1) { X = xk; bias = bk; out = g_K; mat = 1; }
    else                      { X = xv; bias = bv; out = g_V; mat = 2; }

    const int tid  = threadIdx.x;
    const int warp = tid >> 5, lane = tid & 31;
    const int g    = lane >> 2, t4 = lane & 3;
    const int wm   = warp >> 1;
    const int wn   = warp & 1;
    const int m0   = blockIdx.x * 64;

    const float* gwf = g_Wf + (size_t)mat * 256 * 128 * 8;

    float acc[8][4] = {};

    auto issue = [&](int sidx) {
        const int s  = sidx % PJ_DEPTH;
        const int k0 = sidx * 32;
#pragma unroll
        for (int t = 0; t < 2; ++t) {
            int i = tid + t * 256;
            int r = i >> 3, c4 = (i & 7) * 4;
            cpa16(s2u(&Xs[(s * 64 + r) * XSTR + c4]),
                  X + (size_t)(m0 + r) * DMODEL + k0 + c4);
        }
#pragma unroll
        for (int t = 0; t < 4; ++t) {
            int i = tid + t * 256;
            int kb = i >> 8;
            int rem = i & 255;
            int n = rem >> 1, half = rem & 1;
            cpa16(s2u(&WfS[((s * 4 + kb) * 128 + n) * 8 + half * 4]),
                  gwf + (((size_t)(k0 >> 3) + kb) * 128 + n) * 8 + half * 4);
        }
        cp_commit();
    };

    issue(0); issue(1);

    const int NK = DMODEL / 32;   // 64 stages
    for (int i = 0; i < NK; ++i) {
        if (i + 2 < NK) { cp_wait<1>(); } else { cp_wait<0>(); }
        __syncthreads();
        if (i + 2 < NK) issue(i + 2);

        const int s = i % PJ_DEPTH;
        const float* Xc = &Xs[s * XS_FL];
        const float* Wc = &WfS[s * WF_FL];

#pragma unroll
        for (int kk = 0; kk < 4; ++kk) {
            uint32_t a[4];
            {
                int r = wm * 16 + g;
                int c = kk * 8 + t4;
                a[0] = f2tf(Xc[r * XSTR + c]);
                a[1] = f2tf(Xc[(r + 8) * XSTR + c]);
                a[2] = f2tf(Xc[r * XSTR + c + 4]);
                a[3] = f2tf(Xc[(r + 8) * XSTR + c + 4]);
            }
#pragma unroll
            for (int nt = 0; nt < 8; ++nt) {
                int n = wn * 64 + nt * 8 + g;
                float2 w2 = *(const float2*)&Wc[(kk * 128 + n) * 8 + t4 * 2];
                mma_tf32(acc[nt], a, __float_as_uint(w2.x), __float_as_uint(w2.y));
            }
        }
    }

#pragma unroll
    for (int nt = 0; nt < 8; ++nt) {
        int r = m0 + wm * 16 + g;
        int c = wn * 64 + nt * 8 + t4 * 2;
        float b0 = bias[c], b1 = bias[c + 1];
        out[(size_t)r * DH + c]           = __uint_as_float(f2tf(acc[nt][0] + b0));
        out[(size_t)r * DH + c + 1]       = __uint_as_float(f2tf(acc[nt][1] + b1));
        out[(size_t)(r + 8) * DH + c]     = __uint_as_float(f2tf(acc[nt][2] + b0));
        out[(size_t)(r + 8) * DH + c + 1] = __uint_as_float(f2tf(acc[nt][3] + b1));
    }
}

// ---------------------------------------------------------------------------
// Split-KV causal flash attention. grid = (64, 16), 128 thr.
// CHUNK=256 -> max 8 serial tiles per block (was 16).
// Heavy-first schedule: qt = 63 - blockIdx.x so deep q-tiles launch first.
// ---------------------------------------------------------------------------
#define BM 64
#define BN 32
#define KSTR 132   // bank = (4n + k) % 32, conflict-free
#define VSTR 136   // bank = (8k + n) % 32, conflict-free

__global__ __launch_bounds__(128, 2)
void attn_kernel(float* __restrict__ out) {
    const int qt = 63 - blockIdx.x;        // heavy (deep) q-tiles first
    const int ch = blockIdx.y;
    const int nc = (qt >> 2) + 1;          // ceil(64(qt+1)/256)
    if (ch >= nc) return;

    __shared__ float Ks[BN][KSTR];
    __shared__ float Vs[BN][VSTR];
    __shared__ float Ps[4][16][36];

    const int tid  = threadIdx.x;
    const int warp = tid >> 5, lane = tid & 31;
    const int g    = lane >> 2, t4 = lane & 3;
    const int qm0  = qt * BM;
    const int row_base = qm0 + warp * 16;
    const float NEG_INF = __int_as_float(0xff800000u);
    const float SC = 0.02209708691207961f * 1.4426950408889634f;  // (1/sqrt(2048))*log2(e)

    const int kstart = ch * CHUNK;
    const int kend   = min(kstart + CHUNK, qm0 + BM);
    const int ntiles = (kend - kstart) / BN;

    // Q fragments: already tf32-rounded by proj -> raw bits
    uint32_t qf[16][4];
#pragma unroll
    for (int kt = 0; kt < 16; ++kt) {
        const float* qp = g_Q + (size_t)(row_base + g) * DH + kt * 8 + t4;
        qf[kt][0] = __float_as_uint(qp[0]);
        qf[kt][1] = __float_as_uint(qp[8 * DH]);
        qf[kt][2] = __float_as_uint(qp[4]);
        qf[kt][3] = __float_as_uint(qp[8 * DH + 4]);
    }

    float acc[16][4] = {};
    float m0r = NEG_INF, m1r = NEG_INF;
    float l0 = 0.f, l1 = 0.f;

    for (int j = 0; j < ntiles; ++j) {
        const int n0 = kstart + j * BN;

        // stage K/V tile (32 x 128)
#pragma unroll
        for (int t = 0; t < 8; ++t) {
            int i = tid + t * 128;
            int r = i >> 5, c4 = (i & 31) * 4;
            *(float4*)&Ks[r][c4] = *(const float4*)(g_K + (size_t)(n0 + r) * DH + c4);
            *(float4*)&Vs[r][c4] = *(const float4*)(g_V + (size_t)(n0 + r) * DH + c4);
        }
        __syncthreads();

        // S = Q . K^T  (16 x 32 per warp); K bits already tf32
        float s[4][4] = {};
#pragma unroll
        for (int kt = 0; kt < 16; ++kt) {
#pragma unroll
            for (int nt = 0; nt < 4; ++nt) {
                int n = nt * 8 + g;
                int c = kt * 8 + t4;
                uint32_t b0 = __float_as_uint(Ks[n][c]);
                uint32_t b1 = __float_as_uint(Ks[n][c + 4]);
                mma_tf32(s[nt], qf[kt], b0, b1);
            }
        }

        // exp2-domain scale + causal mask
        const int r0g = row_base + g, r1g = r0g + 8;
        const bool domask = (n0 + BN - 1 > row_base);
#pragma unroll
        for (int nt = 0; nt < 4; ++nt) {
            int c0 = n0 + nt * 8 + t4 * 2;
#pragma unroll
            for (int e = 0; e < 4; ++e) s[nt][e] *= SC;
            if (domask) {
                if (c0 > r0g)     s[nt][0] = NEG_INF;
                if (c0 + 1 > r0g) s[nt][1] = NEG_INF;
                if (c0 > r1g)     s[nt][2] = NEG_INF;
                if (c0 + 1 > r1g) s[nt][3] = NEG_INF;
            }
        }

        // online softmax (quad = 4 threads per row)
        float mx0 = fmaxf(fmaxf(s[0][0], s[0][1]), fmaxf(s[1][0], s[1][1]));
        mx0 = fmaxf(mx0, fmaxf(fmaxf(s[2][0], s[2][1]), fmaxf(s[3][0], s[3][1])));
        float mx1 = fmaxf(fmaxf(s[0][2], s[0][3]), fmaxf(s[1][2], s[1][3]));
        mx1 = fmaxf(mx1, fmaxf(fmaxf(s[2][2], s[2][3]), fmaxf(s[3][2], s[3][3])));
        mx0 = fmaxf(mx0, __shfl_xor_sync(0xffffffffu, mx0, 1));
        mx0 = fmaxf(mx0, __shfl_xor_sync(0xffffffffu, mx0, 2));
        mx1 = fmaxf(mx1, __shfl_xor_sync(0xffffffffu, mx1, 1));
        mx1 = fmaxf(mx1, __shfl_xor_sync(0xffffffffu, mx1, 2));

        float mn0 = fmaxf(m0r, mx0), mn1 = fmaxf(m1r, mx1);
        float mu0 = fmaxf(mn0, -1e30f), mu1 = fmaxf(mn1, -1e30f);
        float al0 = ex2(m0r - mu0), al1 = ex2(m1r - mu1);
        m0r = mn0; m1r = mn1;

        float rs0 = 0.f, rs1 = 0.f;
#pragma unroll
        for (int nt = 0; nt < 4; ++nt) {
            float p00 = ex2(s[nt][0] - mu0), p01 = ex2(s[nt][1] - mu0);
            float p10 = ex2(s[nt][2] - mu1), p11 = ex2(s[nt][3] - mu1);
            rs0 += p00 + p01; rs1 += p10 + p11;
            Ps[warp][g][nt * 8 + t4 * 2]         = __uint_as_float(f2tf(p00));
            Ps[warp][g][nt * 8 + t4 * 2 + 1]     = __uint_as_float(f2tf(p01));
            Ps[warp][g + 8][nt * 8 + t4 * 2]     = __uint_as_float(f2tf(p10));
            Ps[warp][g + 8][nt * 8 + t4 * 2 + 1] = __uint_as_float(f2tf(p11));
        }
        rs0 += __shfl_xor_sync(0xffffffffu, rs0, 1);
        rs0 += __shfl_xor_sync(0xffffffffu, rs0, 2);
        rs1 += __shfl_xor_sync(0xffffffffu, rs1, 1);
        rs1 += __shfl_xor_sync(0xffffffffu, rs1, 2);
        l0 = l0 * al0 + rs0;
        l1 = l1 * al1 + rs1;

#pragma unroll
        for (int nt = 0; nt < 16; ++nt) {
            acc[nt][0] *= al0; acc[nt][1] *= al0;
            acc[nt][2] *= al1; acc[nt][3] *= al1;
        }
        __syncwarp();

        // O += P . V
#pragma unroll
        for (int ks = 0; ks < 4; ++ks) {
            uint32_t a[4];
            a[0] = __float_as_uint(Ps[warp][g][ks * 8 + t4]);
            a[1] = __float_as_uint(Ps[warp][g + 8][ks * 8 + t4]);
            a[2] = __float_as_uint(Ps[warp][g][ks * 8 + t4 + 4]);
            a[3] = __float_as_uint(Ps[warp][g + 8][ks * 8 + t4 + 4]);
#pragma unroll
            for (int nt = 0; nt < 16; ++nt) {
                int vn = nt * 8 + g;
                int vk = ks * 8 + t4;
                uint32_t b0 = __float_as_uint(Vs[vk][vn]);
                uint32_t b1 = __float_as_uint(Vs[vk + 4][vn]);
                mma_tf32(acc[nt], a, b0, b1);
            }
        }
        __syncthreads();
    }

    if (nc == 1) {
        // single chunk (qt < 4): write final normalized output
        const float inv0 = 1.0f / l0, inv1 = 1.0f / l1;
#pragma unroll
        for (int nt = 0; nt < 16; ++nt) {
            int r = row_base + g;
            int c = nt * 8 + t4 * 2;
            out[(size_t)r * DH + c]           = acc[nt][0] * inv0;
            out[(size_t)r * DH + c + 1]       = acc[nt][1] * inv0;
            out[(size_t)(r + 8) * DH + c]     = acc[nt][2] * inv1;
            out[(size_t)(r + 8) * DH + c + 1] = acc[nt][3] * inv1;
        }
    } else {
        const int pslot = qt * MAXC + ch;
        float* Op = g_Opart + (size_t)pslot * 64 * DH;
        const int lr0 = warp * 16 + g, lr1 = lr0 + 8;
#pragma unroll
        for (int nt = 0; nt < 16; ++nt) {
            int c = nt * 8 + t4 * 2;
            Op[(size_t)lr0 * DH + c]     = acc[nt][0];
            Op[(size_t)lr0 * DH + c + 1] = acc[nt][1];
            Op[(size_t)lr1 * DH + c]     = acc[nt][2];
            Op[(size_t)lr1 * DH + c + 1] = acc[nt][3];
        }
        if (t4 == 0) {
            g_mpart[pslot * 64 + lr0] = m0r;
            g_lpart[pslot * 64 + lr0] = l0;
            g_mpart[pslot * 64 + lr1] = m1r;
            g_lpart[pslot * 64 + lr1] = l1;
        }
    }
}

// ---------------------------------------------------------------------------
// Combine partials for rows 256..4095 (q-tiles with >= 2 chunks).
// grid = 3840 blocks of 128 threads; one block per row, one thread per col.
// ---------------------------------------------------------------------------
__global__ __launch_bounds__(128)
void combine_kernel(float* __restrict__ out) {
    const int row = 256 + blockIdx.x;
    const int qt  = row >> 6;
    const int nc  = (qt >> 2) + 1;
    const int lr  = row & 63;
    const int col = threadIdx.x;

    float M = -1e30f;
    for (int c = 0; c < nc; ++c)
        M = fmaxf(M, g_mpart[(qt * MAXC + c) * 64 + lr]);

    float l = 0.f, o = 0.f;
    for (int c = 0; c < nc; ++c) {
        int pslot = qt * MAXC + c;
        float a = ex2(g_mpart[pslot * 64 + lr] - M);
        l += a * g_lpart[pslot * 64 + lr];
        o += a * g_Opart[((size_t)pslot * 64 + lr) * DH + col];
    }
    out[(size_t)row * DH + col] = o / l;
}

// ---------------------------------------------------------------------------

extern "C" void kernel_launch(void* const* d_in, const int* in_sizes, int n_in,
                              void* d_out, int out_size) {
    (void)in_sizes; (void)n_in; (void)out_size;
    const float* xq = (const float*)d_in[0];
    const float* xk = (const float*)d_in[1];
    const float* xv = (const float*)d_in[2];
    const float* wq = (const float*)d_in[3];
    const float* bq = (const float*)d_in[4];
    const float* wk = (const float*)d_in[5];
    const float* bk = (const float*)d_in[6];
    const float* wv = (const float*)d_in[7];
    const float* bv = (const float*)d_in[8];
    float* out = (float*)d_out;

    cudaFuncSetAttribute(proj_kernel, cudaFuncAttributeMaxDynamicSharedMemorySize, PJ_SMEM);

    prep_w<<<1536, 256>>>(wq, wk, wv);
    proj_kernel<<<dim3(SEQ / 64, 3), 256, PJ_SMEM>>>(xq, xk, xv, bq, bk, bv);
    attn_kernel<<<dim3(64, MAXC), 128>>>(out);
    combine_kernel<<<SEQ - 256, 128>>>(out);
}

// round 12
// speedup vs baseline: 1.0661x; 1.0661x over previous
#include <cuda_runtime.h>
#include <cstdint>
#include <cstddef>

#define SEQ     4096
#define DMODEL  2048
#define DH      128
#define CHUNK   512          // keys per split-KV work unit
#define MAXC    8            // max chunks per q-tile (4096/512)

// Scratch (allocation-free rule: __device__ globals)
__device__ float g_Q[SEQ * DH];
__device__ float g_K[SEQ * DH];
__device__ float g_V[SEQ * DH];
// W pre-converted to tf32, fragment-pair order: [3][256 kb][128 n][4 t4][2]
__device__ float g_Wf[3 * 256 * 128 * 8];
// proj K-split partials: [2 ksplit][3 mat][4096][128]
__device__ float g_Ppart[2 * 3 * SEQ * DH];
// split-KV partials
__device__ float g_Opart[64 * MAXC * 64 * DH];
__device__ float g_mpart[64 * MAXC * 64];
__device__ float g_lpart[64 * MAXC * 64];

__device__ __forceinline__ uint32_t f2tf(float x) {
    uint32_t r;
    asm("cvt.rna.tf32.f32 %0, %1;" : "=r"(r) : "f"(x));
    return r;
}
__device__ __forceinline__ float ex2(float x) {
    float y;
    asm("ex2.approx.ftz.f32 %0, %1;" : "=f"(y) : "f"(x));
    return y;
}
__device__ __forceinline__ void mma_tf32(float d[4], const uint32_t a[4],
                                         uint32_t b0, uint32_t b1) {
    asm volatile(
        "mma.sync.aligned.m16n8k8.row.col.f32.tf32.tf32.f32 "
        "{%0,%1,%2,%3},{%4,%5,%6,%7},{%8,%9},{%0,%1,%2,%3};\n"
        : "+f"(d[0]), "+f"(d[1]), "+f"(d[2]), "+f"(d[3])
        : "r"(a[0]), "r"(a[1]), "r"(a[2]), "r"(a[3]), "r"(b0), "r"(b1));
}
__device__ __forceinline__ void cpa16(uint32_t dst, const void* src) {
    asm volatile("cp.async.cg.shared.global [%0], [%1], 16;\n" :: "r"(dst), "l"(src));
}
__device__ __forceinline__ void cp_commit() {
    asm volatile("cp.async.commit_group;\n" ::);
}
template <int N>
__device__ __forceinline__ void cp_wait() {
    asm volatile("cp.async.wait_group %0;\n" :: "n"(N));
}
__device__ __forceinline__ uint32_t s2u(const void* p) {
    return (uint32_t)__cvta_generic_to_shared(p);
}

// ---------------------------------------------------------------------------
// prep_w: round W to tf32 and reorder into MMA b-fragment pairs:
// g_Wf[mat][kb][n][t4][2] = { W[n][8kb+t4], W[n][8kb+t4+4] }
// ---------------------------------------------------------------------------
__global__ __launch_bounds__(256)
void prep_w(const float* __restrict__ wq, const float* __restrict__ wk,
            const float* __restrict__ wv) {
    int id = blockIdx.x * 256 + threadIdx.x;       // 0 .. 393215
    int mat = id >> 17;
    int rem = id & 131071;
    int kb = rem >> 9;
    int rem2 = rem & 511;
    int n = rem2 >> 2;
    int t4 = rem2 & 3;
    const float* W = (mat == 0) ? wq : (mat == 1) ? wk : wv;
    float a = W[(size_t)n * DMODEL + kb * 8 + t4];
    float b = W[(size_t)n * DMODEL + kb * 8 + t4 + 4];
    float2 o;
    o.x = __uint_as_float(f2tf(a));
    o.y = __uint_as_float(f2tf(b));
    *(float2*)&g_Wf[(((size_t)mat * 256 + kb) * 128 + n) * 8 + t4 * 2] = o;
}

// ---------------------------------------------------------------------------
// Projection v5: K-split GEMM. Tile 128(M) x 128(N), K-half = 1024.
// grid (32 mtiles, 3 mats, 2 ksplits) = 192 blocks, 256 thr, occ 2.
// cp.async pipeline depth 4, K-step 16. Each b-fragment feeds 2 MMAs (mt 0/1).
// Raw partial sums -> g_Ppart; reduce_qkv adds halves + bias + tf32 round.
// ---------------------------------------------------------------------------
#define PJ_DEPTH 4
#define X2STR    20   // bank = (20g + t4) % 32, all distinct -> conflict-free
#define XS2_FL   (128 * X2STR)      // floats per X stage
#define WF2_FL   (2 * 128 * 8)      // floats per W stage (2 kb)
#define PJ_SMEM  (PJ_DEPTH * (XS2_FL + WF2_FL) * 4)   // 73728 B

__global__ __launch_bounds__(256, 2)
void proj_kernel(const float* __restrict__ xq, const float* __restrict__ xk,
                 const float* __restrict__ xv) {
    extern __shared__ float sm[];
    float* Xs  = sm;                          // [4][128][20]
    float* WfS = sm + PJ_DEPTH * XS2_FL;      // [4][2][128][8]

    const int mat = blockIdx.y;
    const int ks  = blockIdx.z;
    const float* X = (mat == 0) ? xq : (mat == 1) ? xk : xv;

    const int tid  = threadIdx.x;
    const int warp = tid >> 5, lane = tid & 31;
    const int g    = lane >> 2, t4 = lane & 3;
    const int wm   = warp >> 1;   // 0..3 : 32 M-rows each
    const int wn   = warp & 1;    // 0..1 : 64 N-cols each
    const int m0   = blockIdx.x * 128;
    const int kbase = ks * 1024;

    const float* gwf = g_Wf + (size_t)mat * 256 * 128 * 8;

    float acc[2][8][4] = {};

    // stage sidx covers K [kbase + 16*sidx, +16), slot sidx % 4
    auto issue = [&](int sidx) {
        const int s  = sidx & (PJ_DEPTH - 1);
        const int k0 = kbase + sidx * 16;
        // X: 128 rows x 16 floats = 512 16B chunks -> 2 per thread
#pragma unroll
        for (int t = 0; t < 2; ++t) {
            int i = tid + t * 256;
            int r = i >> 2, c4 = (i & 3) * 4;
            cpa16(s2u(&Xs[(s * 128 + r) * X2STR + c4]),
                  X + (size_t)(m0 + r) * DMODEL + k0 + c4);
        }
        // W frags: 2 kb x 128 n x 8 fl = 512 16B chunks -> 2 per thread
#pragma unroll
        for (int t = 0; t < 2; ++t) {
            int i = tid + t * 256;
            int kbl = i >> 8;
            int rem = i & 255;
            int n = rem >> 1, half = rem & 1;
            cpa16(s2u(&WfS[((s * 2 + kbl) * 128 + n) * 8 + half * 4]),
                  gwf + (((size_t)(k0 >> 3) + kbl) * 128 + n) * 8 + half * 4);
        }
        cp_commit();
    };

    issue(0); issue(1); issue(2);

    const int NK = 1024 / 16;   // 64 stages
    for (int i = 0; i < NK; ++i) {
        if (i + 3 < NK) { cp_wait<2>(); } else { cp_wait<0>(); }
        __syncthreads();
        if (i + 3 < NK) issue(i + 3);

        const int s = i & (PJ_DEPTH - 1);
        const float* Xc = &Xs[s * XS2_FL];
        const float* Wc = &WfS[s * WF2_FL];

#pragma unroll
        for (int kk = 0; kk < 2; ++kk) {     // K-step 8 within the stage
            uint32_t a[2][4];
#pragma unroll
            for (int mt = 0; mt < 2; ++mt) {
                int r = wm * 32 + mt * 16 + g;
                int c = kk * 8 + t4;
                a[mt][0] = f2tf(Xc[r * X2STR + c]);
                a[mt][1] = f2tf(Xc[(r + 8) * X2STR + c]);
                a[mt][2] = f2tf(Xc[r * X2STR + c + 4]);
                a[mt][3] = f2tf(Xc[(r + 8) * X2STR + c + 4]);
            }
#pragma unroll
            for (int nt = 0; nt < 8; ++nt) {
                int n = wn * 64 + nt * 8 + g;
                float2 w2 = *(const float2*)&Wc[(kk * 128 + n) * 8 + t4 * 2];
                uint32_t b0 = __float_as_uint(w2.x);
                uint32_t b1 = __float_as_uint(w2.y);
                mma_tf32(acc[0][nt], a[0], b0, b1);
                mma_tf32(acc[1][nt], a[1], b0, b1);
            }
        }
    }

    // raw partials (no bias, no rounding) -> g_Ppart[ks][mat]
    float* P = g_Ppart + ((size_t)(ks * 3 + mat)) * SEQ * DH;
#pragma unroll
    for (int mt = 0; mt < 2; ++mt) {
#pragma unroll
        for (int nt = 0; nt < 8; ++nt) {
            int r = m0 + wm * 32 + mt * 16 + g;
            int c = wn * 64 + nt * 8 + t4 * 2;
            P[(size_t)r * DH + c]           = acc[mt][nt][0];
            P[(size_t)r * DH + c + 1]       = acc[mt][nt][1];
            P[(size_t)(r + 8) * DH + c]     = acc[mt][nt][2];
            P[(size_t)(r + 8) * DH + c + 1] = acc[mt][nt][3];
        }
    }
}

// ---------------------------------------------------------------------------
// reduce_qkv: out = tf32(P0 + P1 + bias), float4-vectorized.
// grid = 1536 blocks x 256 thr; each thread handles 4 consecutive cols.
// ---------------------------------------------------------------------------
__global__ __launch_bounds__(256)
void reduce_qkv(const float* __restrict__ bq, const float* __restrict__ bk,
                const float* __restrict__ bv) {
    int id = blockIdx.x * 256 + threadIdx.x;       // 0 .. 393215 (x4 floats)
    int mat = id / (SEQ * DH / 4);
    int rem = id % (SEQ * DH / 4);                 // float4 index within matrix
    const float* bias = (mat == 0) ? bq : (mat == 1) ? bk : bv;
    float* out = (mat == 0) ? g_Q : (mat == 1) ? g_K : g_V;
    int c4 = (rem & 31) * 4;                       // column (DH/4 = 32 float4s)

    float4 p0 = *(const float4*)&g_Ppart[((size_t)(0 * 3 + mat)) * SEQ * DH + rem * 4];
    float4 p1 = *(const float4*)&g_Ppart[((size_t)(1 * 3 + mat)) * SEQ * DH + rem * 4];
    float4 b  = *(const float4*)&bias[c4];
    float4 o;
    o.x = __uint_as_float(f2tf(p0.x + p1.x + b.x));
    o.y = __uint_as_float(f2tf(p0.y + p1.y + b.y));
    o.z = __uint_as_float(f2tf(p0.z + p1.z + b.z));
    o.w = __uint_as_float(f2tf(p0.w + p1.w + b.w));
    *(float4*)&out[(size_t)rem * 4] = o;
}

// ---------------------------------------------------------------------------
// Split-KV causal flash attention (exact R10 version from the 127.6 run).
// grid = (64 q-tiles, 8 chunks), 128 thr.
// ---------------------------------------------------------------------------
#define BM 64
#define BN 32
#define KSTR 132   // bank = (4n + k) % 32, conflict-free
#define VSTR 136   // bank = (8k + n) % 32, conflict-free

__global__ __launch_bounds__(128, 2)
void attn_kernel(float* __restrict__ out) {
    const int qt = blockIdx.x;
    const int ch = blockIdx.y;
    const int nc = (qt >> 3) + 1;          // ceil(64(qt+1)/512)
    if (ch >= nc) return;

    __shared__ float Ks[BN][KSTR];
    __shared__ float Vs[BN][VSTR];
    __shared__ float Ps[4][16][36];

    const int tid  = threadIdx.x;
    const int warp = tid >> 5, lane = tid & 31;
    const int g    = lane >> 2, t4 = lane & 3;
    const int qm0  = qt * BM;
    const int row_base = qm0 + warp * 16;
    const float NEG_INF = __int_as_float(0xff800000u);
    const float SC = 0.02209708691207961f * 1.4426950408889634f;  // (1/sqrt(2048))*log2(e)

    const int kstart = ch * CHUNK;
    const int kend   = min(kstart + CHUNK, qm0 + BM);
    const int ntiles = (kend - kstart) / BN;

    // Q fragments: already tf32-rounded -> raw bits
    uint32_t qf[16][4];
#pragma unroll
    for (int kt = 0; kt < 16; ++kt) {
        const float* qp = g_Q + (size_t)(row_base + g) * DH + kt * 8 + t4;
        qf[kt][0] = __float_as_uint(qp[0]);
        qf[kt][1] = __float_as_uint(qp[8 * DH]);
        qf[kt][2] = __float_as_uint(qp[4]);
        qf[kt][3] = __float_as_uint(qp[8 * DH + 4]);
    }

    float acc[16][4] = {};
    float m0r = NEG_INF, m1r = NEG_INF;
    float l0 = 0.f, l1 = 0.f;

    for (int j = 0; j < ntiles; ++j) {
        const int n0 = kstart + j * BN;

        // stage K/V tile (32 x 128)
#pragma unroll
        for (int t = 0; t < 8; ++t) {
            int i = tid + t * 128;
            int r = i >> 5, c4 = (i & 31) * 4;
            *(float4*)&Ks[r][c4] = *(const float4*)(g_K + (size_t)(n0 + r) * DH + c4);
            *(float4*)&Vs[r][c4] = *(const float4*)(g_V + (size_t)(n0 + r) * DH + c4);
        }
        __syncthreads();

        // S = Q . K^T  (16 x 32 per warp)
        float s[4][4] = {};
#pragma unroll
        for (int kt = 0; kt < 16; ++kt) {
#pragma unroll
            for (int nt = 0; nt < 4; ++nt) {
                int n = nt * 8 + g;
                int c = kt * 8 + t4;
                uint32_t b0 = __float_as_uint(Ks[n][c]);
                uint32_t b1 = __float_as_uint(Ks[n][c + 4]);
                mma_tf32(s[nt], qf[kt], b0, b1);
            }
        }

        // exp2-domain scale + causal mask
        const int r0g = row_base + g, r1g = r0g + 8;
        const bool domask = (n0 + BN - 1 > row_base);
#pragma unroll
        for (int nt = 0; nt < 4; ++nt) {
            int c0 = n0 + nt * 8 + t4 * 2;
#pragma unroll
            for (int e = 0; e < 4; ++e) s[nt][e] *= SC;
            if (domask) {
                if (c0 > r0g)     s[nt][0] = NEG_INF;
                if (c0 + 1 > r0g) s[nt][1] = NEG_INF;
                if (c0 > r1g)     s[nt][2] = NEG_INF;
                if (c0 + 1 > r1g) s[nt][3] = NEG_INF;
            }
        }

        // online softmax (quad = 4 threads per row)
        float mx0 = fmaxf(fmaxf(s[0][0], s[0][1]), fmaxf(s[1][0], s[1][1]));
        mx0 = fmaxf(mx0, fmaxf(fmaxf(s[2][0], s[2][1]), fmaxf(s[3][0], s[3][1])));
        float mx1 = fmaxf(fmaxf(s[0][2], s[0][3]), fmaxf(s[1][2], s[1][3]));
        mx1 = fmaxf(mx1, fmaxf(fmaxf(s[2][2], s[2][3]), fmaxf(s[3][2], s[3][3])));
        mx0 = fmaxf(mx0, __shfl_xor_sync(0xffffffffu, mx0, 1));
        mx0 = fmaxf(mx0, __shfl_xor_sync(0xffffffffu, mx0, 2));
        mx1 = fmaxf(mx1, __shfl_xor_sync(0xffffffffu, mx1, 1));
        mx1 = fmaxf(mx1, __shfl_xor_sync(0xffffffffu, mx1, 2));

        float mn0 = fmaxf(m0r, mx0), mn1 = fmaxf(m1r, mx1);
        float mu0 = fmaxf(mn0, -1e30f), mu1 = fmaxf(mn1, -1e30f);
        float al0 = ex2(m0r - mu0), al1 = ex2(m1r - mu1);
        m0r = mn0; m1r = mn1;

        float rs0 = 0.f, rs1 = 0.f;
#pragma unroll
        for (int nt = 0; nt < 4; ++nt) {
            float p00 = ex2(s[nt][0] - mu0), p01 = ex2(s[nt][1] - mu0);
            float p10 = ex2(s[nt][2] - mu1), p11 = ex2(s[nt][3] - mu1);
            rs0 += p00 + p01; rs1 += p10 + p11;
            Ps[warp][g][nt * 8 + t4 * 2]         = __uint_as_float(f2tf(p00));
            Ps[warp][g][nt * 8 + t4 * 2 + 1]     = __uint_as_float(f2tf(p01));
            Ps[warp][g + 8][nt * 8 + t4 * 2]     = __uint_as_float(f2tf(p10));
            Ps[warp][g + 8][nt * 8 + t4 * 2 + 1] = __uint_as_float(f2tf(p11));
        }
        rs0 += __shfl_xor_sync(0xffffffffu, rs0, 1);
        rs0 += __shfl_xor_sync(0xffffffffu, rs0, 2);
        rs1 += __shfl_xor_sync(0xffffffffu, rs1, 1);
        rs1 += __shfl_xor_sync(0xffffffffu, rs1, 2);
        l0 = l0 * al0 + rs0;
        l1 = l1 * al1 + rs1;

#pragma unroll
        for (int nt = 0; nt < 16; ++nt) {
            acc[nt][0] *= al0; acc[nt][1] *= al0;
            acc[nt][2] *= al1; acc[nt][3] *= al1;
        }
        __syncwarp();

        // O += P . V
#pragma unroll
        for (int ks = 0; ks < 4; ++ks) {
            uint32_t a[4];
            a[0] = __float_as_uint(Ps[warp][g][ks * 8 + t4]);
            a[1] = __float_as_uint(Ps[warp][g + 8][ks * 8 + t4]);
            a[2] = __float_as_uint(Ps[warp][g][ks * 8 + t4 + 4]);
            a[3] = __float_as_uint(Ps[warp][g + 8][ks * 8 + t4 + 4]);
#pragma unroll
            for (int nt = 0; nt < 16; ++nt) {
                int vn = nt * 8 + g;
                int vk = ks * 8 + t4;
                uint32_t b0 = __float_as_uint(Vs[vk][vn]);
                uint32_t b1 = __float_as_uint(Vs[vk + 4][vn]);
                mma_tf32(acc[nt], a, b0, b1);
            }
        }
        __syncthreads();
    }

    if (nc == 1) {
        const float inv0 = 1.0f / l0, inv1 = 1.0f / l1;
#pragma unroll
        for (int nt = 0; nt < 16; ++nt) {
            int r = row_base + g;
            int c = nt * 8 + t4 * 2;
            out[(size_t)r * DH + c]           = acc[nt][0] * inv0;
            out[(size_t)r * DH + c + 1]       = acc[nt][1] * inv0;
            out[(size_t)(r + 8) * DH + c]     = acc[nt][2] * inv1;
            out[(size_t)(r + 8) * DH + c + 1] = acc[nt][3] * inv1;
        }
    } else {
        const int pslot = qt * MAXC + ch;
        float* Op = g_Opart + (size_t)pslot * 64 * DH;
        const int lr0 = warp * 16 + g, lr1 = lr0 + 8;
#pragma unroll
        for (int nt = 0; nt < 16; ++nt) {
            int c = nt * 8 + t4 * 2;
            Op[(size_t)lr0 * DH + c]     = acc[nt][0];
            Op[(size_t)lr0 * DH + c + 1] = acc[nt][1];
            Op[(size_t)lr1 * DH + c]     = acc[nt][2];
            Op[(size_t)lr1 * DH + c + 1] = acc[nt][3];
        }
        if (t4 == 0) {
            g_mpart[pslot * 64 + lr0] = m0r;
            g_lpart[pslot * 64 + lr0] = l0;
            g_mpart[pslot * 64 + lr1] = m1r;
            g_lpart[pslot * 64 + lr1] = l1;
        }
    }
}

// ---------------------------------------------------------------------------
// Combine partials for rows 512..4095 (q-tiles with >= 2 chunks).
// ---------------------------------------------------------------------------
__global__ __launch_bounds__(128)
void combine_kernel(float* __restrict__ out) {
    const int row = 512 + blockIdx.x;
    const int qt  = row >> 6;
    const int nc  = (qt >> 3) + 1;
    const int lr  = row & 63;
    const int col = threadIdx.x;

    float M = -1e30f;
    for (int c = 0; c < nc; ++c)
        M = fmaxf(M, g_mpart[(qt * MAXC + c) * 64 + lr]);

    float l = 0.f, o = 0.f;
    for (int c = 0; c < nc; ++c) {
        int pslot = qt * MAXC + c;
        float a = ex2(g_mpart[pslot * 64 + lr] - M);
        l += a * g_lpart[pslot * 64 + lr];
        o += a * g_Opart[((size_t)pslot * 64 + lr) * DH + col];
    }
    out[(size_t)row * DH + col] = o / l;
}

// ---------------------------------------------------------------------------

extern "C" void kernel_launch(void* const* d_in, const int* in_sizes, int n_in,
                              void* d_out, int out_size) {
    (void)in_sizes; (void)n_in; (void)out_size;
    const float* xq = (const float*)d_in[0];
    const float* xk = (const float*)d_in[1];
    const float* xv = (const float*)d_in[2];
    const float* wq = (const float*)d_in[3];
    const float* bq = (const float*)d_in[4];
    const float* wk = (const float*)d_in[5];
    const float* bk = (const float*)d_in[6];
    const float* wv = (const float*)d_in[7];
    const float* bv = (const float*)d_in[8];
    float* out = (float*)d_out;

    cudaFuncSetAttribute(proj_kernel, cudaFuncAttributeMaxDynamicSharedMemorySize, PJ_SMEM);

    prep_w<<<1536, 256>>>(wq, wk, wv);
    proj_kernel<<<dim3(32, 3, 2), 256, PJ_SMEM>>>(xq, xk, xv);
    reduce_qkv<<<1536, 256>>>(bq, bk, bv);
    attn_kernel<<<dim3(SEQ / BM, MAXC), 128>>>(out);
    combine_kernel<<<SEQ - 512, 128>>>(out);
}

// round 13
// speedup vs baseline: 1.1334x; 1.0632x over previous
#include <cuda_runtime.h>
#include <cuda_fp16.h>
#include <cstdint>
#include <cstddef>

#define SEQ     4096
#define DMODEL  2048
#define DH      128
#define CHUNK   512          // keys per split-KV work unit
#define MAXC    8            // max chunks per q-tile (4096/512)

// Scratch (allocation-free rule: __device__ globals)
// fp16 activations (10-bit mantissa == tf32; accumulate in f32)
__device__ __align__(16) __half g_Qh[SEQ * DH];          // [row][col]
__device__ __align__(16) __half g_Kh[SEQ * DH];          // [row][col]
__device__ __align__(16) __half g_Vh[SEQ * DH];          // [tile32][col][key-in-tile] (transposed per tile)
// W pre-converted to tf32, fragment-pair order: [3][256 kb][128 n][4 t4][2]
__device__ float g_Wf[3 * 256 * 128 * 8];
// proj K-split partials: [2 ksplit][3 mat][4096][128]
__device__ float g_Ppart[2 * 3 * SEQ * DH];
// split-KV partials
__device__ float g_Opart[64 * MAXC * 64 * DH];
__device__ float g_mpart[64 * MAXC * 64];
__device__ float g_lpart[64 * MAXC * 64];

__device__ __forceinline__ uint32_t f2tf(float x) {
    uint32_t r;
    asm("cvt.rna.tf32.f32 %0, %1;" : "=r"(r) : "f"(x));
    return r;
}
__device__ __forceinline__ float ex2(float x) {
    float y;
    asm("ex2.approx.ftz.f32 %0, %1;" : "=f"(y) : "f"(x));
    return y;
}
__device__ __forceinline__ void mma_tf32(float d[4], const uint32_t a[4],
                                         uint32_t b0, uint32_t b1) {
    asm volatile(
        "mma.sync.aligned.m16n8k8.row.col.f32.tf32.tf32.f32 "
        "{%0,%1,%2,%3},{%4,%5,%6,%7},{%8,%9},{%0,%1,%2,%3};\n"
        : "+f"(d[0]), "+f"(d[1]), "+f"(d[2]), "+f"(d[3])
        : "r"(a[0]), "r"(a[1]), "r"(a[2]), "r"(a[3]), "r"(b0), "r"(b1));
}
__device__ __forceinline__ void mma_f16(float d[4], const uint32_t a[4],
                                        uint32_t b0, uint32_t b1) {
    asm volatile(
        "mma.sync.aligned.m16n8k16.row.col.f32.f16.f16.f32 "
        "{%0,%1,%2,%3},{%4,%5,%6,%7},{%8,%9},{%0,%1,%2,%3};\n"
        : "+f"(d[0]), "+f"(d[1]), "+f"(d[2]), "+f"(d[3])
        : "r"(a[0]), "r"(a[1]), "r"(a[2]), "r"(a[3]), "r"(b0), "r"(b1));
}
__device__ __forceinline__ void cpa16(uint32_t dst, const void* src) {
    asm volatile("cp.async.cg.shared.global [%0], [%1], 16;\n" :: "r"(dst), "l"(src));
}
__device__ __forceinline__ void cp_commit() {
    asm volatile("cp.async.commit_group;\n" ::);
}
template <int N>
__device__ __forceinline__ void cp_wait() {
    asm volatile("cp.async.wait_group %0;\n" :: "n"(N));
}
__device__ __forceinline__ uint32_t s2u(const void* p) {
    return (uint32_t)__cvta_generic_to_shared(p);
}

// ---------------------------------------------------------------------------
// prep_w (unchanged): W -> tf32 fragment pairs.
// ---------------------------------------------------------------------------
__global__ __launch_bounds__(256)
void prep_w(const float* __restrict__ wq, const float* __restrict__ wk,
            const float* __restrict__ wv) {
    int id = blockIdx.x * 256 + threadIdx.x;       // 0 .. 393215
    int mat = id >> 17;
    int rem = id & 131071;
    int kb = rem >> 9;
    int rem2 = rem & 511;
    int n = rem2 >> 2;
    int t4 = rem2 & 3;
    const float* W = (mat == 0) ? wq : (mat == 1) ? wk : wv;
    float a = W[(size_t)n * DMODEL + kb * 8 + t4];
    float b = W[(size_t)n * DMODEL + kb * 8 + t4 + 4];
    float2 o;
    o.x = __uint_as_float(f2tf(a));
    o.y = __uint_as_float(f2tf(b));
    *(float2*)&g_Wf[(((size_t)mat * 256 + kb) * 128 + n) * 8 + t4 * 2] = o;
}

// ---------------------------------------------------------------------------
// Projection v5 (unchanged from 124.9 build): K-split 128x128 tiles,
// grid (32,3,2), cp.async depth 4, raw partials -> g_Ppart.
// ---------------------------------------------------------------------------
#define PJ_DEPTH 4
#define X2STR    20
#define XS2_FL   (128 * X2STR)
#define WF2_FL   (2 * 128 * 8)
#define PJ_SMEM  (PJ_DEPTH * (XS2_FL + WF2_FL) * 4)   // 73728 B

__global__ __launch_bounds__(256, 2)
void proj_kernel(const float* __restrict__ xq, const float* __restrict__ xk,
                 const float* __restrict__ xv) {
    extern __shared__ float sm[];
    float* Xs  = sm;
    float* WfS = sm + PJ_DEPTH * XS2_FL;

    const int mat = blockIdx.y;
    const int ks  = blockIdx.z;
    const float* X = (mat == 0) ? xq : (mat == 1) ? xk : xv;

    const int tid  = threadIdx.x;
    const int warp = tid >> 5, lane = tid & 31;
    const int g    = lane >> 2, t4 = lane & 3;
    const int wm   = warp >> 1;
    const int wn   = warp & 1;
    const int m0   = blockIdx.x * 128;
    const int kbase = ks * 1024;

    const float* gwf = g_Wf + (size_t)mat * 256 * 128 * 8;

    float acc[2][8][4] = {};

    auto issue = [&](int sidx) {
        const int s  = sidx & (PJ_DEPTH - 1);
        const int k0 = kbase + sidx * 16;
#pragma unroll
        for (int t = 0; t < 2; ++t) {
            int i = tid + t * 256;
            int r = i >> 2, c4 = (i & 3) * 4;
            cpa16(s2u(&Xs[(s * 128 + r) * X2STR + c4]),
                  X + (size_t)(m0 + r) * DMODEL + k0 + c4);
        }
#pragma unroll
        for (int t = 0; t < 2; ++t) {
            int i = tid + t * 256;
            int kbl = i >> 8;
            int rem = i & 255;
            int n = rem >> 1, half = rem & 1;
            cpa16(s2u(&WfS[((s * 2 + kbl) * 128 + n) * 8 + half * 4]),
                  gwf + (((size_t)(k0 >> 3) + kbl) * 128 + n) * 8 + half * 4);
        }
        cp_commit();
    };

    issue(0); issue(1); issue(2);

    const int NK = 1024 / 16;
    for (int i = 0; i < NK; ++i) {
        if (i + 3 < NK) { cp_wait<2>(); } else { cp_wait<0>(); }
        __syncthreads();
        if (i + 3 < NK) issue(i + 3);

        const int s = i & (PJ_DEPTH - 1);
        const float* Xc = &Xs[s * XS2_FL];
        const float* Wc = &WfS[s * WF2_FL];

#pragma unroll
        for (int kk = 0; kk < 2; ++kk) {
            uint32_t a[2][4];
#pragma unroll
            for (int mt = 0; mt < 2; ++mt) {
                int r = wm * 32 + mt * 16 + g;
                int c = kk * 8 + t4;
                a[mt][0] = f2tf(Xc[r * X2STR + c]);
                a[mt][1] = f2tf(Xc[(r + 8) * X2STR + c]);
                a[mt][2] = f2tf(Xc[r * X2STR + c + 4]);
                a[mt][3] = f2tf(Xc[(r + 8) * X2STR + c + 4]);
            }
#pragma unroll
            for (int nt = 0; nt < 8; ++nt) {
                int n = wn * 64 + nt * 8 + g;
                float2 w2 = *(const float2*)&Wc[(kk * 128 + n) * 8 + t4 * 2];
                uint32_t b0 = __float_as_uint(w2.x);
                uint32_t b1 = __float_as_uint(w2.y);
                mma_tf32(acc[0][nt], a[0], b0, b1);
                mma_tf32(acc[1][nt], a[1], b0, b1);
            }
        }
    }

    float* P = g_Ppart + ((size_t)(ks * 3 + mat)) * SEQ * DH;
#pragma unroll
    for (int mt = 0; mt < 2; ++mt) {
#pragma unroll
        for (int nt = 0; nt < 8; ++nt) {
            int r = m0 + wm * 32 + mt * 16 + g;
            int c = wn * 64 + nt * 8 + t4 * 2;
            P[(size_t)r * DH + c]           = acc[mt][nt][0];
            P[(size_t)r * DH + c + 1]       = acc[mt][nt][1];
            P[(size_t)(r + 8) * DH + c]     = acc[mt][nt][2];
            P[(size_t)(r + 8) * DH + c + 1] = acc[mt][nt][3];
        }
    }
}

// ---------------------------------------------------------------------------
// reduce_qkv: sum K-split halves + bias, emit fp16:
//   Q, K -> natural [row][col] halfs;  V -> per-32-row-tile transposed
//   [tile][col][key-in-tile] (so PV b-fragments pair adjacent keys).
// ---------------------------------------------------------------------------
__global__ __launch_bounds__(256)
void reduce_qkv(const float* __restrict__ bq, const float* __restrict__ bk,
                const float* __restrict__ bv) {
    int id = blockIdx.x * 256 + threadIdx.x;       // 0 .. 393215
    int mat = id / (SEQ * DH / 4);
    int rem = id % (SEQ * DH / 4);
    const float* bias = (mat == 0) ? bq : (mat == 1) ? bk : bv;
    int row = rem >> 5;
    int c4  = (rem & 31) * 4;

    float4 p0 = *(const float4*)&g_Ppart[((size_t)(0 * 3 + mat)) * SEQ * DH + (size_t)rem * 4];
    float4 p1 = *(const float4*)&g_Ppart[((size_t)(1 * 3 + mat)) * SEQ * DH + (size_t)rem * 4];
    float4 b  = *(const float4*)&bias[c4];
    float v0 = p0.x + p1.x + b.x;
    float v1 = p0.y + p1.y + b.y;
    float v2 = p0.z + p1.z + b.z;
    float v3 = p0.w + p1.w + b.w;

    if (mat < 2) {
        __half* dst = (mat == 0) ? g_Qh : g_Kh;
        __half2 lo = __floats2half2_rn(v0, v1);
        __half2 hi = __floats2half2_rn(v2, v3);
        uint2 val;
        val.x = *(uint32_t*)&lo;
        val.y = *(uint32_t*)&hi;
        *(uint2*)(dst + (size_t)row * DH + c4) = val;
    } else {
        int tile = row >> 5, lr = row & 31;
        size_t base = ((size_t)tile * 128) * 32;
        g_Vh[base + (size_t)(c4 + 0) * 32 + lr] = __float2half_rn(v0);
        g_Vh[base + (size_t)(c4 + 1) * 32 + lr] = __float2half_rn(v1);
        g_Vh[base + (size_t)(c4 + 2) * 32 + lr] = __float2half_rn(v2);
        g_Vh[base + (size_t)(c4 + 3) * 32 + lr] = __float2half_rn(v3);
    }
}

// ---------------------------------------------------------------------------
// Split-KV causal flash attention, fp16 operands (m16n8k16), fp32 softmax+acc.
// grid = (64 q-tiles, 8 chunks), 128 thr. Same schedule as the 124.9 build.
// smem (uint32 = half2 units): Ks2[32][68], Vs2[128][20], Ps2[4][16][20]
//   — strides chosen so every LDS.32 instruction hits 32 distinct banks.
// ---------------------------------------------------------------------------
#define BM 64
#define BN 32

__global__ __launch_bounds__(128, 2)
void attn_kernel(float* __restrict__ out) {
    const int qt = blockIdx.x;
    const int ch = blockIdx.y;
    const int nc = (qt >> 3) + 1;          // ceil(64(qt+1)/512)
    if (ch >= nc) return;

    __shared__ uint32_t Ks2[32][68];       // [key][col-pair]  (+4 pad)
    __shared__ uint32_t Vs2[128][20];      // [col][key-pair]  (+4 pad)
    __shared__ uint32_t Ps2[4][16][20];    // [warp][row][key-pair] (+4 pad)

    const int tid  = threadIdx.x;
    const int warp = tid >> 5, lane = tid & 31;
    const int g    = lane >> 2, t4 = lane & 3;
    const int qm0  = qt * BM;
    const int row_base = qm0 + warp * 16;
    const float NEG_INF = __int_as_float(0xff800000u);
    const float SC = 0.02209708691207961f * 1.4426950408889634f;  // (1/sqrt(2048))*log2(e)

    const int kstart = ch * CHUNK;
    const int kend   = min(kstart + CHUNK, qm0 + BM);
    const int ntiles = (kend - kstart) / BN;

    // Q fragments, fp16 pairs straight from g_Qh (adjacent cols = half2)
    const uint32_t* qh32 = (const uint32_t*)g_Qh;
    uint32_t qf[8][4];
    {
        const int r0 = row_base + g, r1 = r0 + 8;
#pragma unroll
        for (int kt2 = 0; kt2 < 8; ++kt2) {
            qf[kt2][0] = qh32[(size_t)r0 * 64 + kt2 * 8 + t4];
            qf[kt2][1] = qh32[(size_t)r1 * 64 + kt2 * 8 + t4];
            qf[kt2][2] = qh32[(size_t)r0 * 64 + kt2 * 8 + t4 + 4];
            qf[kt2][3] = qh32[(size_t)r1 * 64 + kt2 * 8 + t4 + 4];
        }
    }

    float acc[16][4] = {};
    float m0r = NEG_INF, m1r = NEG_INF;
    float l0 = 0.f, l1 = 0.f;

    for (int j = 0; j < ntiles; ++j) {
        const int n0 = kstart + j * BN;
        const int vtile = n0 >> 5;

        // stage K (32x128 fp16, row-major pairs) + V (transposed tile)
#pragma unroll
        for (int t = 0; t < 4; ++t) {
            int i = tid + t * 128;
            int r = i >> 4, grp = i & 15;
            *(uint4*)&Ks2[r][grp * 4] =
                *(const uint4*)(g_Kh + ((size_t)(n0 + r)) * DH + grp * 8);
        }
#pragma unroll
        for (int t = 0; t < 4; ++t) {
            int i = tid + t * 128;
            int col = i >> 2, grp = i & 3;
            *(uint4*)&Vs2[col][grp * 4] =
                *(const uint4*)(g_Vh + (((size_t)vtile * 128 + col) * 32) + grp * 8);
        }
        __syncthreads();

        // S = Q . K^T  (16 x 32 per warp), fp16 m16n8k16
        float s[4][4] = {};
#pragma unroll
        for (int kt2 = 0; kt2 < 8; ++kt2) {
#pragma unroll
            for (int nt = 0; nt < 4; ++nt) {
                int n = nt * 8 + g;
                uint32_t b0 = Ks2[n][kt2 * 8 + t4];
                uint32_t b1 = Ks2[n][kt2 * 8 + t4 + 4];
                mma_f16(s[nt], qf[kt2], b0, b1);
            }
        }

        // exp2-domain scale + causal mask
        const int r0g = row_base + g, r1g = r0g + 8;
        const bool domask = (n0 + BN - 1 > row_base);
#pragma unroll
        for (int nt = 0; nt < 4; ++nt) {
            int c0 = n0 + nt * 8 + t4 * 2;
#pragma unroll
            for (int e = 0; e < 4; ++e) s[nt][e] *= SC;
            if (domask) {
                if (c0 > r0g)     s[nt][0] = NEG_INF;
                if (c0 + 1 > r0g) s[nt][1] = NEG_INF;
                if (c0 > r1g)     s[nt][2] = NEG_INF;
                if (c0 + 1 > r1g) s[nt][3] = NEG_INF;
            }
        }

        // online softmax (quad = 4 threads per row)
        float mx0 = fmaxf(fmaxf(s[0][0], s[0][1]), fmaxf(s[1][0], s[1][1]));
        mx0 = fmaxf(mx0, fmaxf(fmaxf(s[2][0], s[2][1]), fmaxf(s[3][0], s[3][1])));
        float mx1 = fmaxf(fmaxf(s[0][2], s[0][3]), fmaxf(s[1][2], s[1][3]));
        mx1 = fmaxf(mx1, fmaxf(fmaxf(s[2][2], s[2][3]), fmaxf(s[3][2], s[3][3])));
        mx0 = fmaxf(mx0, __shfl_xor_sync(0xffffffffu, mx0, 1));
        mx0 = fmaxf(mx0, __shfl_xor_sync(0xffffffffu, mx0, 2));
        mx1 = fmaxf(mx1, __shfl_xor_sync(0xffffffffu, mx1, 1));
        mx1 = fmaxf(mx1, __shfl_xor_sync(0xffffffffu, mx1, 2));

        float mn0 = fmaxf(m0r, mx0), mn1 = fmaxf(m1r, mx1);
        float mu0 = fmaxf(mn0, -1e30f), mu1 = fmaxf(mn1, -1e30f);
        float al0 = ex2(m0r - mu0), al1 = ex2(m1r - mu1);
        m0r = mn0; m1r = mn1;

        float rs0 = 0.f, rs1 = 0.f;
#pragma unroll
        for (int nt = 0; nt < 4; ++nt) {
            float p00 = ex2(s[nt][0] - mu0), p01 = ex2(s[nt][1] - mu0);
            float p10 = ex2(s[nt][2] - mu1), p11 = ex2(s[nt][3] - mu1);
            rs0 += p00 + p01; rs1 += p10 + p11;
            __half2 h0 = __floats2half2_rn(p00, p01);
            __half2 h1 = __floats2half2_rn(p10, p11);
            Ps2[warp][g][nt * 4 + t4]     = *(uint32_t*)&h0;
            Ps2[warp][g + 8][nt * 4 + t4] = *(uint32_t*)&h1;
        }
        rs0 += __shfl_xor_sync(0xffffffffu, rs0, 1);
        rs0 += __shfl_xor_sync(0xffffffffu, rs0, 2);
        rs1 += __shfl_xor_sync(0xffffffffu, rs1, 1);
        rs1 += __shfl_xor_sync(0xffffffffu, rs1, 2);
        l0 = l0 * al0 + rs0;
        l1 = l1 * al1 + rs1;

#pragma unroll
        for (int nt = 0; nt < 16; ++nt) {
            acc[nt][0] *= al0; acc[nt][1] *= al0;
            acc[nt][2] *= al1; acc[nt][3] *= al1;
        }
        __syncwarp();

        // O += P . V  (fp16 m16n8k16: 2 k-steps of 16 keys)
#pragma unroll
        for (int ks2 = 0; ks2 < 2; ++ks2) {
            uint32_t a[4];
            a[0] = Ps2[warp][g][ks2 * 8 + t4];
            a[1] = Ps2[warp][g + 8][ks2 * 8 + t4];
            a[2] = Ps2[warp][g][ks2 * 8 + t4 + 4];
            a[3] = Ps2[warp][g + 8][ks2 * 8 + t4 + 4];
#pragma unroll
            for (int nt = 0; nt < 16; ++nt) {
                int vn = nt * 8 + g;
                uint32_t b0 = Vs2[vn][ks2 * 8 + t4];
                uint32_t b1 = Vs2[vn][ks2 * 8 + t4 + 4];
                mma_f16(acc[nt], a, b0, b1);
            }
        }
        __syncthreads();
    }

    if (nc == 1) {
        const float inv0 = 1.0f / l0, inv1 = 1.0f / l1;
#pragma unroll
        for (int nt = 0; nt < 16; ++nt) {
            int r = row_base + g;
            int c = nt * 8 + t4 * 2;
            out[(size_t)r * DH + c]           = acc[nt][0] * inv0;
            out[(size_t)r * DH + c + 1]       = acc[nt][1] * inv0;
            out[(size_t)(r + 8) * DH + c]     = acc[nt][2] * inv1;
            out[(size_t)(r + 8) * DH + c + 1] = acc[nt][3] * inv1;
        }
    } else {
        const int pslot = qt * MAXC + ch;
        float* Op = g_Opart + (size_t)pslot * 64 * DH;
        const int lr0 = warp * 16 + g, lr1 = lr0 + 8;
#pragma unroll
        for (int nt = 0; nt < 16; ++nt) {
            int c = nt * 8 + t4 * 2;
            Op[(size_t)lr0 * DH + c]     = acc[nt][0];
            Op[(size_t)lr0 * DH + c + 1] = acc[nt][1];
            Op[(size_t)lr1 * DH + c]     = acc[nt][2];
            Op[(size_t)lr1 * DH + c + 1] = acc[nt][3];
        }
        if (t4 == 0) {
            g_mpart[pslot * 64 + lr0] = m0r;
            g_lpart[pslot * 64 + lr0] = l0;
            g_mpart[pslot * 64 + lr1] = m1r;
            g_lpart[pslot * 64 + lr1] = l1;
        }
    }
}

// ---------------------------------------------------------------------------
// Combine partials for rows 512..4095 (unchanged).
// ---------------------------------------------------------------------------
__global__ __launch_bounds__(128)
void combine_kernel(float* __restrict__ out) {
    const int row = 512 + blockIdx.x;
    const int qt  = row >> 6;
    const int nc  = (qt >> 3) + 1;
    const int lr  = row & 63;
    const int col = threadIdx.x;

    float M = -1e30f;
    for (int c = 0; c < nc; ++c)
        M = fmaxf(M, g_mpart[(qt * MAXC + c) * 64 + lr]);

    float l = 0.f, o = 0.f;
    for (int c = 0; c < nc; ++c) {
        int pslot = qt * MAXC + c;
        float a = ex2(g_mpart[pslot * 64 + lr] - M);
        l += a * g_lpart[pslot * 64 + lr];
        o += a * g_Opart[((size_t)pslot * 64 + lr) * DH + col];
    }
    out[(size_t)row * DH + col] = o / l;
}

// ---------------------------------------------------------------------------

extern "C" void kernel_launch(void* const* d_in, const int* in_sizes, int n_in,
                              void* d_out, int out_size) {
    (void)in_sizes; (void)n_in; (void)out_size;
    const float* xq = (const float*)d_in[0];
    const float* xk = (const float*)d_in[1];
    const float* xv = (const float*)d_in[2];
    const float* wq = (const float*)d_in[3];
    const float* bq = (const float*)d_in[4];
    const float* wk = (const float*)d_in[5];
    const float* bk = (const float*)d_in[6];
    const float* wv = (const float*)d_in[7];
    const float* bv = (const float*)d_in[8];
    float* out = (float*)d_out;

    cudaFuncSetAttribute(proj_kernel, cudaFuncAttributeMaxDynamicSharedMemorySize, PJ_SMEM);

    prep_w<<<1536, 256>>>(wq, wk, wv);
    proj_kernel<<<dim3(32, 3, 2), 256, PJ_SMEM>>>(xq, xk, xv);
    reduce_qkv<<<1536, 256>>>(bq, bk, bv);
    attn_kernel<<<dim3(SEQ / BM, MAXC), 128>>>(out);
    combine_kernel<<<SEQ - 512, 128>>>(out);
}

// round 14
// speedup vs baseline: 1.5771x; 1.3914x over previous
#include <cuda_runtime.h>
#include <cuda_fp16.h>
#include <cstdint>
#include <cstddef>

#define SEQ     4096
#define DMODEL  2048
#define DH      128
#define CHUNK   512          // keys per split-KV work unit
#define MAXC    8            // max chunks per q-tile (4096/512)

// Scratch (allocation-free rule: __device__ globals)
__device__ __align__(16) __half g_Qh[SEQ * DH];          // [row][col]
__device__ __align__(16) __half g_Kh[SEQ * DH];          // [row][col]
__device__ __align__(16) __half g_Vh[SEQ * DH];          // [tile32][col][key-in-tile]
// W as fp16 m16n8k16 b-fragment pairs:
// [mat][kb16 0..127][n 0..127][t4 0..3][2]  (u32 = half2 units)
__device__ __align__(16) uint32_t g_Whf[3 * 128 * 128 * 8];
// proj K-split partials: [2 ksplit][3 mat][4096][128]
__device__ float g_Ppart[2 * 3 * SEQ * DH];
// split-KV partials
__device__ float g_Opart[64 * MAXC * 64 * DH];
__device__ float g_mpart[64 * MAXC * 64];
__device__ float g_lpart[64 * MAXC * 64];

__device__ __forceinline__ float ex2(float x) {
    float y;
    asm("ex2.approx.ftz.f32 %0, %1;" : "=f"(y) : "f"(x));
    return y;
}
__device__ __forceinline__ void mma_f16(float d[4], const uint32_t a[4],
                                        uint32_t b0, uint32_t b1) {
    asm volatile(
        "mma.sync.aligned.m16n8k16.row.col.f32.f16.f16.f32 "
        "{%0,%1,%2,%3},{%4,%5,%6,%7},{%8,%9},{%0,%1,%2,%3};\n"
        : "+f"(d[0]), "+f"(d[1]), "+f"(d[2]), "+f"(d[3])
        : "r"(a[0]), "r"(a[1]), "r"(a[2]), "r"(a[3]), "r"(b0), "r"(b1));
}
__device__ __forceinline__ void cpa16(uint32_t dst, const void* src) {
    asm volatile("cp.async.cg.shared.global [%0], [%1], 16;\n" :: "r"(dst), "l"(src));
}
__device__ __forceinline__ void cp_commit() {
    asm volatile("cp.async.commit_group;\n" ::);
}
template <int N>
__device__ __forceinline__ void cp_wait() {
    asm volatile("cp.async.wait_group %0;\n" :: "n"(N));
}
__device__ __forceinline__ uint32_t s2u(const void* p) {
    return (uint32_t)__cvta_generic_to_shared(p);
}
__device__ __forceinline__ uint32_t packh2(float x, float y) {
    __half2 h = __floats2half2_rn(x, y);
    return *(uint32_t*)&h;
}

// ---------------------------------------------------------------------------
// prep_w: W -> fp16 k16 b-fragment pairs.
// [kb][n][t4][0] = {W[n][16kb+2t4], W[n][16kb+2t4+1]}
// [kb][n][t4][1] = {W[n][16kb+8+2t4], W[n][16kb+8+2t4+1]}
// ---------------------------------------------------------------------------
__global__ __launch_bounds__(256)
void prep_w(const float* __restrict__ wq, const float* __restrict__ wk,
            const float* __restrict__ wv) {
    int id = blockIdx.x * 256 + threadIdx.x;       // 0 .. 196607
    int mat = id / (128 * 128 * 4);
    int rem = id % (128 * 128 * 4);
    int kb = rem >> 9;
    int rem2 = rem & 511;
    int n = rem2 >> 2;
    int t4 = rem2 & 3;
    const float* W = (mat == 0) ? wq : (mat == 1) ? wk : wv;
    const float* wr = W + (size_t)n * DMODEL + kb * 16;
    uint2 o;
    o.x = packh2(wr[2 * t4],     wr[2 * t4 + 1]);
    o.y = packh2(wr[8 + 2 * t4], wr[8 + 2 * t4 + 1]);
    *(uint2*)&g_Whf[(((size_t)mat * 128 + kb) * 128 + n) * 8 + t4 * 2] = o;
}

// ---------------------------------------------------------------------------
// Projection v6: fp16 m16n8k16, 64(M) x 128(N) tile, 128 thr, occ 4.
// grid (64 mtiles, 3 mats, 2 ksplits) = 384 CTAs -> one balanced wave.
// smem/stage: Xs fp32 [64][24] (6KB, cvt+pack at use) + Wh u32 [128][8] (4KB).
// depth-4 cp.async, K-step 16, wait_group<2>.
// ---------------------------------------------------------------------------
#define PJ_DEPTH 4
#define XSTRH    24                      // fp32 words per X smem row
#define XS_FL    (64 * XSTRH)            // 1536 floats / stage
#define WS_U32   (128 * 8)               // 1024 u32 / stage
#define PJ_SMEM  (PJ_DEPTH * (XS_FL * 4 + WS_U32 * 4))   // 40960 B

__global__ __launch_bounds__(128, 4)
void proj_kernel(const float* __restrict__ xq, const float* __restrict__ xk,
                 const float* __restrict__ xv) {
    extern __shared__ float sm[];
    float*    Xs = sm;                                   // [4][64][24]
    uint32_t* Wh = (uint32_t*)(sm + PJ_DEPTH * XS_FL);   // [4][128][8]

    const int mat = blockIdx.y;
    const int ks  = blockIdx.z;
    const float* X = (mat == 0) ? xq : (mat == 1) ? xk : xv;

    const int tid  = threadIdx.x;
    const int warp = tid >> 5, lane = tid & 31;
    const int g    = lane >> 2, t4 = lane & 3;
    const int wm   = warp >> 1;   // 0..1 : 32 M-rows each
    const int wn   = warp & 1;    // 0..1 : 64 N-cols each
    const int m0   = blockIdx.x * 64;

    const uint32_t* gwh = g_Whf + (size_t)mat * 128 * 128 * 8;

    float acc[2][8][4] = {};

    // stage sidx covers K16 group kb = ks*64 + sidx; slot sidx % 4
    auto issue = [&](int sidx) {
        const int s  = sidx & (PJ_DEPTH - 1);
        const int k0 = ks * 1024 + sidx * 16;
        // X: 64 rows x 16 floats = 256 16B chunks -> 2 per thread
#pragma unroll
        for (int t = 0; t < 2; ++t) {
            int i = tid + t * 128;
            int r = i >> 2, c4 = (i & 3) * 4;
            cpa16(s2u(&Xs[(s * 64 + r) * XSTRH + c4]),
                  X + (size_t)(m0 + r) * DMODEL + k0 + c4);
        }
        // W: 128 n x 8 u32 = 256 16B chunks -> 2 per thread
#pragma unroll
        for (int t = 0; t < 2; ++t) {
            int i = tid + t * 128;
            int n = i >> 1, half = i & 1;
            cpa16(s2u(&Wh[(s * 128 + n) * 8 + half * 4]),
                  gwh + (((size_t)(ks * 64 + sidx)) * 128 + n) * 8 + half * 4);
        }
        cp_commit();
    };

    issue(0); issue(1); issue(2);

    const int NK = 64;   // 1024 / 16
    for (int i = 0; i < NK; ++i) {
        if (i + 3 < NK) { cp_wait<2>(); } else { cp_wait<0>(); }
        __syncthreads();
        if (i + 3 < NK) issue(i + 3);

        const int s = i & (PJ_DEPTH - 1);
        const float*    Xc = &Xs[s * XS_FL];
        const uint32_t* Wc = &Wh[s * WS_U32];

        // a-fragments: fp32 smem -> half2 pack  (one k16 step)
        uint32_t a[2][4];
#pragma unroll
        for (int mt = 0; mt < 2; ++mt) {
            int r = wm * 32 + mt * 16 + g;
            float2 x0 = *(const float2*)&Xc[r * XSTRH + 2 * t4];
            float2 x1 = *(const float2*)&Xc[(r + 8) * XSTRH + 2 * t4];
            float2 x2 = *(const float2*)&Xc[r * XSTRH + 2 * t4 + 8];
            float2 x3 = *(const float2*)&Xc[(r + 8) * XSTRH + 2 * t4 + 8];
            a[mt][0] = packh2(x0.x, x0.y);
            a[mt][1] = packh2(x1.x, x1.y);
            a[mt][2] = packh2(x2.x, x2.y);
            a[mt][3] = packh2(x3.x, x3.y);
        }
#pragma unroll
        for (int nt = 0; nt < 8; ++nt) {
            int n = wn * 64 + nt * 8 + g;
            uint2 b = *(const uint2*)&Wc[n * 8 + t4 * 2];   // LDS.64, conflict-free
            mma_f16(acc[0][nt], a[0], b.x, b.y);
            mma_f16(acc[1][nt], a[1], b.x, b.y);
        }
    }

    // raw partials -> g_Ppart[ks][mat]
    float* P = g_Ppart + ((size_t)(ks * 3 + mat)) * SEQ * DH;
#pragma unroll
    for (int mt = 0; mt < 2; ++mt) {
#pragma unroll
        for (int nt = 0; nt < 8; ++nt) {
            int r = m0 + wm * 32 + mt * 16 + g;
            int c = wn * 64 + nt * 8 + t4 * 2;
            P[(size_t)r * DH + c]           = acc[mt][nt][0];
            P[(size_t)r * DH + c + 1]       = acc[mt][nt][1];
            P[(size_t)(r + 8) * DH + c]     = acc[mt][nt][2];
            P[(size_t)(r + 8) * DH + c + 1] = acc[mt][nt][3];
        }
    }
}

// ---------------------------------------------------------------------------
// reduce_qkv (unchanged from 117.5 build): sum halves + bias, emit fp16
// Q/K natural, V transposed per 32-row tile.
// ---------------------------------------------------------------------------
__global__ __launch_bounds__(256)
void reduce_qkv(const float* __restrict__ bq, const float* __restrict__ bk,
                const float* __restrict__ bv) {
    int id = blockIdx.x * 256 + threadIdx.x;       // 0 .. 393215
    int mat = id / (SEQ * DH / 4);
    int rem = id % (SEQ * DH / 4);
    const float* bias = (mat == 0) ? bq : (mat == 1) ? bk : bv;
    int row = rem >> 5;
    int c4  = (rem & 31) * 4;

    float4 p0 = *(const float4*)&g_Ppart[((size_t)(0 * 3 + mat)) * SEQ * DH + (size_t)rem * 4];
    float4 p1 = *(const float4*)&g_Ppart[((size_t)(1 * 3 + mat)) * SEQ * DH + (size_t)rem * 4];
    float4 b  = *(const float4*)&bias[c4];
    float v0 = p0.x + p1.x + b.x;
    float v1 = p0.y + p1.y + b.y;
    float v2 = p0.z + p1.z + b.z;
    float v3 = p0.w + p1.w + b.w;

    if (mat < 2) {
        __half* dst = (mat == 0) ? g_Qh : g_Kh;
        uint2 val;
        val.x = packh2(v0, v1);
        val.y = packh2(v2, v3);
        *(uint2*)(dst + (size_t)row * DH + c4) = val;
    } else {
        int tile = row >> 5, lr = row & 31;
        size_t base = ((size_t)tile * 128) * 32;
        g_Vh[base + (size_t)(c4 + 0) * 32 + lr] = __float2half_rn(v0);
        g_Vh[base + (size_t)(c4 + 1) * 32 + lr] = __float2half_rn(v1);
        g_Vh[base + (size_t)(c4 + 2) * 32 + lr] = __float2half_rn(v2);
        g_Vh[base + (size_t)(c4 + 3) * 32 + lr] = __float2half_rn(v3);
    }
}

// ---------------------------------------------------------------------------
// Split-KV causal flash attention (byte-identical to the 117.5 build).
// ---------------------------------------------------------------------------
#define BM 64
#define BN 32

__global__ __launch_bounds__(128, 2)
void attn_kernel(float* __restrict__ out) {
    const int qt = blockIdx.x;
    const int ch = blockIdx.y;
    const int nc = (qt >> 3) + 1;
    if (ch >= nc) return;

    __shared__ uint32_t Ks2[32][68];
    __shared__ uint32_t Vs2[128][20];
    __shared__ uint32_t Ps2[4][16][20];

    const int tid  = threadIdx.x;
    const int warp = tid >> 5, lane = tid & 31;
    const int g    = lane >> 2, t4 = lane & 3;
    const int qm0  = qt * BM;
    const int row_base = qm0 + warp * 16;
    const float NEG_INF = __int_as_float(0xff800000u);
    const float SC = 0.02209708691207961f * 1.4426950408889634f;

    const int kstart = ch * CHUNK;
    const int kend   = min(kstart + CHUNK, qm0 + BM);
    const int ntiles = (kend - kstart) / BN;

    const uint32_t* qh32 = (const uint32_t*)g_Qh;
    uint32_t qf[8][4];
    {
        const int r0 = row_base + g, r1 = r0 + 8;
#pragma unroll
        for (int kt2 = 0; kt2 < 8; ++kt2) {
            qf[kt2][0] = qh32[(size_t)r0 * 64 + kt2 * 8 + t4];
            qf[kt2][1] = qh32[(size_t)r1 * 64 + kt2 * 8 + t4];
            qf[kt2][2] = qh32[(size_t)r0 * 64 + kt2 * 8 + t4 + 4];
            qf[kt2][3] = qh32[(size_t)r1 * 64 + kt2 * 8 + t4 + 4];
        }
    }

    float acc[16][4] = {};
    float m0r = NEG_INF, m1r = NEG_INF;
    float l0 = 0.f, l1 = 0.f;

    for (int j = 0; j < ntiles; ++j) {
        const int n0 = kstart + j * BN;
        const int vtile = n0 >> 5;

#pragma unroll
        for (int t = 0; t < 4; ++t) {
            int i = tid + t * 128;
            int r = i >> 4, grp = i & 15;
            *(uint4*)&Ks2[r][grp * 4] =
                *(const uint4*)(g_Kh + ((size_t)(n0 + r)) * DH + grp * 8);
        }
#pragma unroll
        for (int t = 0; t < 4; ++t) {
            int i = tid + t * 128;
            int col = i >> 2, grp = i & 3;
            *(uint4*)&Vs2[col][grp * 4] =
                *(const uint4*)(g_Vh + (((size_t)vtile * 128 + col) * 32) + grp * 8);
        }
        __syncthreads();

        float s[4][4] = {};
#pragma unroll
        for (int kt2 = 0; kt2 < 8; ++kt2) {
#pragma unroll
            for (int nt = 0; nt < 4; ++nt) {
                int n = nt * 8 + g;
                uint32_t b0 = Ks2[n][kt2 * 8 + t4];
                uint32_t b1 = Ks2[n][kt2 * 8 + t4 + 4];
                mma_f16(s[nt], qf[kt2], b0, b1);
            }
        }

        const int r0g = row_base + g, r1g = r0g + 8;
        const bool domask = (n0 + BN - 1 > row_base);
#pragma unroll
        for (int nt = 0; nt < 4; ++nt) {
            int c0 = n0 + nt * 8 + t4 * 2;
#pragma unroll
            for (int e = 0; e < 4; ++e) s[nt][e] *= SC;
            if (domask) {
                if (c0 > r0g)     s[nt][0] = NEG_INF;
                if (c0 + 1 > r0g) s[nt][1] = NEG_INF;
                if (c0 > r1g)     s[nt][2] = NEG_INF;
                if (c0 + 1 > r1g) s[nt][3] = NEG_INF;
            }
        }

        float mx0 = fmaxf(fmaxf(s[0][0], s[0][1]), fmaxf(s[1][0], s[1][1]));
        mx0 = fmaxf(mx0, fmaxf(fmaxf(s[2][0], s[2][1]), fmaxf(s[3][0], s[3][1])));
        float mx1 = fmaxf(fmaxf(s[0][2], s[0][3]), fmaxf(s[1][2], s[1][3]));
        mx1 = fmaxf(mx1, fmaxf(fmaxf(s[2][2], s[2][3]), fmaxf(s[3][2], s[3][3])));
        mx0 = fmaxf(mx0, __shfl_xor_sync(0xffffffffu, mx0, 1));
        mx0 = fmaxf(mx0, __shfl_xor_sync(0xffffffffu, mx0, 2));
        mx1 = fmaxf(mx1, __shfl_xor_sync(0xffffffffu, mx1, 1));
        mx1 = fmaxf(mx1, __shfl_xor_sync(0xffffffffu, mx1, 2));

        float mn0 = fmaxf(m0r, mx0), mn1 = fmaxf(m1r, mx1);
        float mu0 = fmaxf(mn0, -1e30f), mu1 = fmaxf(mn1, -1e30f);
        float al0 = ex2(m0r - mu0), al1 = ex2(m1r - mu1);
        m0r = mn0; m1r = mn1;

        float rs0 = 0.f, rs1 = 0.f;
#pragma unroll
        for (int nt = 0; nt < 4; ++nt) {
            float p00 = ex2(s[nt][0] - mu0), p01 = ex2(s[nt][1] - mu0);
            float p10 = ex2(s[nt][2] - mu1), p11 = ex2(s[nt][3] - mu1);
            rs0 += p00 + p01; rs1 += p10 + p11;
            Ps2[warp][g][nt * 4 + t4]     = packh2(p00, p01);
            Ps2[warp][g + 8][nt * 4 + t4] = packh2(p10, p11);
        }
        rs0 += __shfl_xor_sync(0xffffffffu, rs0, 1);
        rs0 += __shfl_xor_sync(0xffffffffu, rs0, 2);
        rs1 += __shfl_xor_sync(0xffffffffu, rs1, 1);
        rs1 += __shfl_xor_sync(0xffffffffu, rs1, 2);
        l0 = l0 * al0 + rs0;
        l1 = l1 * al1 + rs1;

#pragma unroll
        for (int nt = 0; nt < 16; ++nt) {
            acc[nt][0] *= al0; acc[nt][1] *= al0;
            acc[nt][2] *= al1; acc[nt][3] *= al1;
        }
        __syncwarp();

#pragma unroll
        for (int ks2 = 0; ks2 < 2; ++ks2) {
            uint32_t a[4];
            a[0] = Ps2[warp][g][ks2 * 8 + t4];
            a[1] = Ps2[warp][g + 8][ks2 * 8 + t4];
            a[2] = Ps2[warp][g][ks2 * 8 + t4 + 4];
            a[3] = Ps2[warp][g + 8][ks2 * 8 + t4 + 4];
#pragma unroll
            for (int nt = 0; nt < 16; ++nt) {
                int vn = nt * 8 + g;
                uint32_t b0 = Vs2[vn][ks2 * 8 + t4];
                uint32_t b1 = Vs2[vn][ks2 * 8 + t4 + 4];
                mma_f16(acc[nt], a, b0, b1);
            }
        }
        __syncthreads();
    }

    if (nc == 1) {
        const float inv0 = 1.0f / l0, inv1 = 1.0f / l1;
#pragma unroll
        for (int nt = 0; nt < 16; ++nt) {
            int r = row_base + g;
            int c = nt * 8 + t4 * 2;
            out[(size_t)r * DH + c]           = acc[nt][0] * inv0;
            out[(size_t)r * DH + c + 1]       = acc[nt][1] * inv0;
            out[(size_t)(r + 8) * DH + c]     = acc[nt][2] * inv1;
            out[(size_t)(r + 8) * DH + c + 1] = acc[nt][3] * inv1;
        }
    } else {
        const int pslot = qt * MAXC + ch;
        float* Op = g_Opart + (size_t)pslot * 64 * DH;
        const int lr0 = warp * 16 + g, lr1 = lr0 + 8;
#pragma unroll
        for (int nt = 0; nt < 16; ++nt) {
            int c = nt * 8 + t4 * 2;
            Op[(size_t)lr0 * DH + c]     = acc[nt][0];
            Op[(size_t)lr0 * DH + c + 1] = acc[nt][1];
            Op[(size_t)lr1 * DH + c]     = acc[nt][2];
            Op[(size_t)lr1 * DH + c + 1] = acc[nt][3];
        }
        if (t4 == 0) {
            g_mpart[pslot * 64 + lr0] = m0r;
            g_lpart[pslot * 64 + lr0] = l0;
            g_mpart[pslot * 64 + lr1] = m1r;
            g_lpart[pslot * 64 + lr1] = l1;
        }
    }
}

// ---------------------------------------------------------------------------
// Combine partials for rows 512..4095 (unchanged).
// ---------------------------------------------------------------------------
__global__ __launch_bounds__(128)
void combine_kernel(float* __restrict__ out) {
    const int row = 512 + blockIdx.x;
    const int qt  = row >> 6;
    const int nc  = (qt >> 3) + 1;
    const int lr  = row & 63;
    const int col = threadIdx.x;

    float M = -1e30f;
    for (int c = 0; c < nc; ++c)
        M = fmaxf(M, g_mpart[(qt * MAXC + c) * 64 + lr]);

    float l = 0.f, o = 0.f;
    for (int c = 0; c < nc; ++c) {
        int pslot = qt * MAXC + c;
        float a = ex2(g_mpart[pslot * 64 + lr] - M);
        l += a * g_lpart[pslot * 64 + lr];
        o += a * g_Opart[((size_t)pslot * 64 + lr) * DH + col];
    }
    out[(size_t)row * DH + col] = o / l;
}

// ---------------------------------------------------------------------------

extern "C" void kernel_launch(void* const* d_in, const int* in_sizes, int n_in,
                              void* d_out, int out_size) {
    (void)in_sizes; (void)n_in; (void)out_size;
    const float* xq = (const float*)d_in[0];
    const float* xk = (const float*)d_in[1];
    const float* xv = (const float*)d_in[2];
    const float* wq = (const float*)d_in[3];
    const float* bq = (const float*)d_in[4];
    const float* wk = (const float*)d_in[5];
    const float* bk = (const float*)d_in[6];
    const float* wv = (const float*)d_in[7];
    const float* bv = (const float*)d_in[8];
    float* out = (float*)d_out;

    cudaFuncSetAttribute(proj_kernel, cudaFuncAttributeMaxDynamicSharedMemorySize, PJ_SMEM);

    prep_w<<<768, 256>>>(wq, wk, wv);
    proj_kernel<<<dim3(64, 3, 2), 128, PJ_SMEM>>>(xq, xk, xv);
    reduce_qkv<<<1536, 256>>>(bq, bk, bv);
    attn_kernel<<<dim3(SEQ / BM, MAXC), 128>>>(out);
    combine_kernel<<<SEQ - 512, 128>>>(out);
}

// round 15
// speedup vs baseline: 1.6045x; 1.0173x over previous
#include <cuda_runtime.h>
#include <cuda_fp16.h>
#include <cstdint>
#include <cstddef>

#define SEQ     4096
#define DMODEL  2048
#define DH      128
#define CHUNK   512          // keys per split-KV work unit
#define MAXC    8            // max chunks per q-tile (4096/512)

// Scratch (allocation-free rule: __device__ globals)
__device__ __align__(16) __half g_Qh[SEQ * DH];          // [row][col]
__device__ __align__(16) __half g_Kh[SEQ * DH];          // [row][col]
__device__ __align__(16) __half g_Vh[SEQ * DH];          // [tile32][col][key-in-tile]
// W as fp16 m16n8k16 b-fragment pairs:
// [mat][kb16 0..127][n 0..127][t4 0..3][2]  (u32 = half2 units)
__device__ __align__(16) uint32_t g_Whf[3 * 128 * 128 * 8];
// split-KV partials
__device__ float g_Opart[64 * MAXC * 64 * DH];
__device__ float g_mpart[64 * MAXC * 64];
__device__ float g_lpart[64 * MAXC * 64];

__device__ __forceinline__ float ex2(float x) {
    float y;
    asm("ex2.approx.ftz.f32 %0, %1;" : "=f"(y) : "f"(x));
    return y;
}
__device__ __forceinline__ void mma_f16(float d[4], const uint32_t a[4],
                                        uint32_t b0, uint32_t b1) {
    asm volatile(
        "mma.sync.aligned.m16n8k16.row.col.f32.f16.f16.f32 "
        "{%0,%1,%2,%3},{%4,%5,%6,%7},{%8,%9},{%0,%1,%2,%3};\n"
        : "+f"(d[0]), "+f"(d[1]), "+f"(d[2]), "+f"(d[3])
        : "r"(a[0]), "r"(a[1]), "r"(a[2]), "r"(a[3]), "r"(b0), "r"(b1));
}
__device__ __forceinline__ void cpa16(uint32_t dst, const void* src) {
    asm volatile("cp.async.cg.shared.global [%0], [%1], 16;\n" :: "r"(dst), "l"(src));
}
__device__ __forceinline__ void cp_commit() {
    asm volatile("cp.async.commit_group;\n" ::);
}
template <int N>
__device__ __forceinline__ void cp_wait() {
    asm volatile("cp.async.wait_group %0;\n" :: "n"(N));
}
__device__ __forceinline__ uint32_t s2u(const void* p) {
    return (uint32_t)__cvta_generic_to_shared(p);
}
__device__ __forceinline__ uint32_t packh2(float x, float y) {
    __half2 h = __floats2half2_rn(x, y);
    return *(uint32_t*)&h;
}

// ---------------------------------------------------------------------------
// prep_w (unchanged): W -> fp16 k16 b-fragment pairs.
// ---------------------------------------------------------------------------
__global__ __launch_bounds__(256)
void prep_w(const float* __restrict__ wq, const float* __restrict__ wk,
            const float* __restrict__ wv) {
    int id = blockIdx.x * 256 + threadIdx.x;       // 0 .. 196607
    int mat = id / (128 * 128 * 4);
    int rem = id % (128 * 128 * 4);
    int kb = rem >> 9;
    int rem2 = rem & 511;
    int n = rem2 >> 2;
    int t4 = rem2 & 3;
    const float* W = (mat == 0) ? wq : (mat == 1) ? wk : wv;
    const float* wr = W + (size_t)n * DMODEL + kb * 16;
    uint2 o;
    o.x = packh2(wr[2 * t4],     wr[2 * t4 + 1]);
    o.y = packh2(wr[8 + 2 * t4], wr[8 + 2 * t4 + 1]);
    *(uint2*)&g_Whf[(((size_t)mat * 128 + kb) * 128 + n) * 8 + t4 * 2] = o;
}

// ---------------------------------------------------------------------------
// Projection v7: fp16 m16n8k16, FULL K=2048 (ksplit removed), fused epilogue:
// bias + fp16 pack + (V) per-32-row-tile transpose, writing attn's exact
// input layouts. 64(M) x 128(N) tile, 128 thr, occ 4, grid (64, 3).
// depth-4 cp.async, K-step 16, wait_group<2>  (same staging as the 84.4 build).
// ---------------------------------------------------------------------------
#define PJ_DEPTH 4
#define XSTRH    24                      // fp32 words per X smem row
#define XS_FL    (64 * XSTRH)            // 1536 floats / stage
#define WS_U32   (128 * 8)               // 1024 u32 / stage
#define PJ_SMEM  (PJ_DEPTH * (XS_FL * 4 + WS_U32 * 4))   // 40960 B

__global__ __launch_bounds__(128, 4)
void proj_kernel(const float* __restrict__ xq, const float* __restrict__ xk,
                 const float* __restrict__ xv,
                 const float* __restrict__ bq, const float* __restrict__ bk,
                 const float* __restrict__ bv) {
    extern __shared__ float sm[];
    float*    Xs = sm;                                   // [4][64][24]
    uint32_t* Wh = (uint32_t*)(sm + PJ_DEPTH * XS_FL);   // [4][128][8]

    const int mat = blockIdx.y;
    const float* X    = (mat == 0) ? xq : (mat == 1) ? xk : xv;
    const float* bias = (mat == 0) ? bq : (mat == 1) ? bk : bv;

    const int tid  = threadIdx.x;
    const int warp = tid >> 5, lane = tid & 31;
    const int g    = lane >> 2, t4 = lane & 3;
    const int wm   = warp >> 1;   // 0..1 : 32 M-rows each
    const int wn   = warp & 1;    // 0..1 : 64 N-cols each
    const int m0   = blockIdx.x * 64;

    const uint32_t* gwh = g_Whf + (size_t)mat * 128 * 128 * 8;

    float acc[2][8][4] = {};

    // stage sidx covers K16 group kb = sidx; slot sidx % 4
    auto issue = [&](int sidx) {
        const int s  = sidx & (PJ_DEPTH - 1);
        const int k0 = sidx * 16;
#pragma unroll
        for (int t = 0; t < 2; ++t) {
            int i = tid + t * 128;
            int r = i >> 2, c4 = (i & 3) * 4;
            cpa16(s2u(&Xs[(s * 64 + r) * XSTRH + c4]),
                  X + (size_t)(m0 + r) * DMODEL + k0 + c4);
        }
#pragma unroll
        for (int t = 0; t < 2; ++t) {
            int i = tid + t * 128;
            int n = i >> 1, half = i & 1;
            cpa16(s2u(&Wh[(s * 128 + n) * 8 + half * 4]),
                  gwh + (((size_t)sidx) * 128 + n) * 8 + half * 4);
        }
        cp_commit();
    };

    issue(0); issue(1); issue(2);

    const int NK = DMODEL / 16;   // 128 stages
    for (int i = 0; i < NK; ++i) {
        if (i + 3 < NK) { cp_wait<2>(); } else { cp_wait<0>(); }
        __syncthreads();
        if (i + 3 < NK) issue(i + 3);

        const int s = i & (PJ_DEPTH - 1);
        const float*    Xc = &Xs[s * XS_FL];
        const uint32_t* Wc = &Wh[s * WS_U32];

        uint32_t a[2][4];
#pragma unroll
        for (int mt = 0; mt < 2; ++mt) {
            int r = wm * 32 + mt * 16 + g;
            float2 x0 = *(const float2*)&Xc[r * XSTRH + 2 * t4];
            float2 x1 = *(const float2*)&Xc[(r + 8) * XSTRH + 2 * t4];
            float2 x2 = *(const float2*)&Xc[r * XSTRH + 2 * t4 + 8];
            float2 x3 = *(const float2*)&Xc[(r + 8) * XSTRH + 2 * t4 + 8];
            a[mt][0] = packh2(x0.x, x0.y);
            a[mt][1] = packh2(x1.x, x1.y);
            a[mt][2] = packh2(x2.x, x2.y);
            a[mt][3] = packh2(x3.x, x3.y);
        }
#pragma unroll
        for (int nt = 0; nt < 8; ++nt) {
            int n = wn * 64 + nt * 8 + g;
            uint2 b = *(const uint2*)&Wc[n * 8 + t4 * 2];   // LDS.64, conflict-free
            mma_f16(acc[0][nt], a[0], b.x, b.y);
            mma_f16(acc[1][nt], a[1], b.x, b.y);
        }
    }

    // fused epilogue: bias + fp16; Q/K natural layout, V transposed per tile
    if (mat < 2) {
        __half* dst = (mat == 0) ? g_Qh : g_Kh;
#pragma unroll
        for (int mt = 0; mt < 2; ++mt) {
#pragma unroll
            for (int nt = 0; nt < 8; ++nt) {
                int r = m0 + wm * 32 + mt * 16 + g;
                int c = wn * 64 + nt * 8 + t4 * 2;
                float b0 = bias[c], b1 = bias[c + 1];
                *(uint32_t*)(dst + (size_t)r * DH + c) =
                    packh2(acc[mt][nt][0] + b0, acc[mt][nt][1] + b1);
                *(uint32_t*)(dst + (size_t)(r + 8) * DH + c) =
                    packh2(acc[mt][nt][2] + b0, acc[mt][nt][3] + b1);
            }
        }
    } else {
#pragma unroll
        for (int mt = 0; mt < 2; ++mt) {
#pragma unroll
            for (int nt = 0; nt < 8; ++nt) {
                int r = m0 + wm * 32 + mt * 16 + g;
                int c = wn * 64 + nt * 8 + t4 * 2;
                float b0 = bias[c], b1 = bias[c + 1];
                size_t base = (size_t)(r >> 5) * (DH * 32);
                int lr = r & 31;
                g_Vh[base + (size_t)c * 32 + lr]            = __float2half_rn(acc[mt][nt][0] + b0);
                g_Vh[base + (size_t)(c + 1) * 32 + lr]      = __float2half_rn(acc[mt][nt][1] + b1);
                g_Vh[base + (size_t)c * 32 + lr + 8]        = __float2half_rn(acc[mt][nt][2] + b0);
                g_Vh[base + (size_t)(c + 1) * 32 + lr + 8]  = __float2half_rn(acc[mt][nt][3] + b1);
            }
        }
    }
}

// ---------------------------------------------------------------------------
// Split-KV causal flash attention (byte-identical to the 84.4 build).
// ---------------------------------------------------------------------------
#define BM 64
#define BN 32

__global__ __launch_bounds__(128, 2)
void attn_kernel(float* __restrict__ out) {
    const int qt = blockIdx.x;
    const int ch = blockIdx.y;
    const int nc = (qt >> 3) + 1;
    if (ch >= nc) return;

    __shared__ uint32_t Ks2[32][68];
    __shared__ uint32_t Vs2[128][20];
    __shared__ uint32_t Ps2[4][16][20];

    const int tid  = threadIdx.x;
    const int warp = tid >> 5, lane = tid & 31;
    const int g    = lane >> 2, t4 = lane & 3;
    const int qm0  = qt * BM;
    const int row_base = qm0 + warp * 16;
    const float NEG_INF = __int_as_float(0xff800000u);
    const float SC = 0.02209708691207961f * 1.4426950408889634f;

    const int kstart = ch * CHUNK;
    const int kend   = min(kstart + CHUNK, qm0 + BM);
    const int ntiles = (kend - kstart) / BN;

    const uint32_t* qh32 = (const uint32_t*)g_Qh;
    uint32_t qf[8][4];
    {
        const int r0 = row_base + g, r1 = r0 + 8;
#pragma unroll
        for (int kt2 = 0; kt2 < 8; ++kt2) {
            qf[kt2][0] = qh32[(size_t)r0 * 64 + kt2 * 8 + t4];
            qf[kt2][1] = qh32[(size_t)r1 * 64 + kt2 * 8 + t4];
            qf[kt2][2] = qh32[(size_t)r0 * 64 + kt2 * 8 + t4 + 4];
            qf[kt2][3] = qh32[(size_t)r1 * 64 + kt2 * 8 + t4 + 4];
        }
    }

    float acc[16][4] = {};
    float m0r = NEG_INF, m1r = NEG_INF;
    float l0 = 0.f, l1 = 0.f;

    for (int j = 0; j < ntiles; ++j) {
        const int n0 = kstart + j * BN;
        const int vtile = n0 >> 5;

#pragma unroll
        for (int t = 0; t < 4; ++t) {
            int i = tid + t * 128;
            int r = i >> 4, grp = i & 15;
            *(uint4*)&Ks2[r][grp * 4] =
                *(const uint4*)(g_Kh + ((size_t)(n0 + r)) * DH + grp * 8);
        }
#pragma unroll
        for (int t = 0; t < 4; ++t) {
            int i = tid + t * 128;
            int col = i >> 2, grp = i & 3;
            *(uint4*)&Vs2[col][grp * 4] =
                *(const uint4*)(g_Vh + (((size_t)vtile * 128 + col) * 32) + grp * 8);
        }
        __syncthreads();

        float s[4][4] = {};
#pragma unroll
        for (int kt2 = 0; kt2 < 8; ++kt2) {
#pragma unroll
            for (int nt = 0; nt < 4; ++nt) {
                int n = nt * 8 + g;
                uint32_t b0 = Ks2[n][kt2 * 8 + t4];
                uint32_t b1 = Ks2[n][kt2 * 8 + t4 + 4];
                mma_f16(s[nt], qf[kt2], b0, b1);
            }
        }

        const int r0g = row_base + g, r1g = r0g + 8;
        const bool domask = (n0 + BN - 1 > row_base);
#pragma unroll
        for (int nt = 0; nt < 4; ++nt) {
            int c0 = n0 + nt * 8 + t4 * 2;
#pragma unroll
            for (int e = 0; e < 4; ++e) s[nt][e] *= SC;
            if (domask) {
                if (c0 > r0g)     s[nt][0] = NEG_INF;
                if (c0 + 1 > r0g) s[nt][1] = NEG_INF;
                if (c0 > r1g)     s[nt][2] = NEG_INF;
                if (c0 + 1 > r1g) s[nt][3] = NEG_INF;
            }
        }

        float mx0 = fmaxf(fmaxf(s[0][0], s[0][1]), fmaxf(s[1][0], s[1][1]));
        mx0 = fmaxf(mx0, fmaxf(fmaxf(s[2][0], s[2][1]), fmaxf(s[3][0], s[3][1])));
        float mx1 = fmaxf(fmaxf(s[0][2], s[0][3]), fmaxf(s[1][2], s[1][3]));
        mx1 = fmaxf(mx1, fmaxf(fmaxf(s[2][2], s[2][3]), fmaxf(s[3][2], s[3][3])));
        mx0 = fmaxf(mx0, __shfl_xor_sync(0xffffffffu, mx0, 1));
        mx0 = fmaxf(mx0, __shfl_xor_sync(0xffffffffu, mx0, 2));
        mx1 = fmaxf(mx1, __shfl_xor_sync(0xffffffffu, mx1, 1));
        mx1 = fmaxf(mx1, __shfl_xor_sync(0xffffffffu, mx1, 2));

        float mn0 = fmaxf(m0r, mx0), mn1 = fmaxf(m1r, mx1);
        float mu0 = fmaxf(mn0, -1e30f), mu1 = fmaxf(mn1, -1e30f);
        float al0 = ex2(m0r - mu0), al1 = ex2(m1r - mu1);
        m0r = mn0; m1r = mn1;

        float rs0 = 0.f, rs1 = 0.f;
#pragma unroll
        for (int nt = 0; nt < 4; ++nt) {
            float p00 = ex2(s[nt][0] - mu0), p01 = ex2(s[nt][1] - mu0);
            float p10 = ex2(s[nt][2] - mu1), p11 = ex2(s[nt][3] - mu1);
            rs0 += p00 + p01; rs1 += p10 + p11;
            Ps2[warp][g][nt * 4 + t4]     = packh2(p00, p01);
            Ps2[warp][g + 8][nt * 4 + t4] = packh2(p10, p11);
        }
        rs0 += __shfl_xor_sync(0xffffffffu, rs0, 1);
        rs0 += __shfl_xor_sync(0xffffffffu, rs0, 2);
        rs1 += __shfl_xor_sync(0xffffffffu, rs1, 1);
        rs1 += __shfl_xor_sync(0xffffffffu, rs1, 2);
        l0 = l0 * al0 + rs0;
        l1 = l1 * al1 + rs1;

#pragma unroll
        for (int nt = 0; nt < 16; ++nt) {
            acc[nt][0] *= al0; acc[nt][1] *= al0;
            acc[nt][2] *= al1; acc[nt][3] *= al1;
        }
        __syncwarp();

#pragma unroll
        for (int ks2 = 0; ks2 < 2; ++ks2) {
            uint32_t a[4];
            a[0] = Ps2[warp][g][ks2 * 8 + t4];
            a[1] = Ps2[warp][g + 8][ks2 * 8 + t4];
            a[2] = Ps2[warp][g][ks2 * 8 + t4 + 4];
            a[3] = Ps2[warp][g + 8][ks2 * 8 + t4 + 4];
#pragma unroll
            for (int nt = 0; nt < 16; ++nt) {
                int vn = nt * 8 + g;
                uint32_t b0 = Vs2[vn][ks2 * 8 + t4];
                uint32_t b1 = Vs2[vn][ks2 * 8 + t4 + 4];
                mma_f16(acc[nt], a, b0, b1);
            }
        }
        __syncthreads();
    }

    if (nc == 1) {
        const float inv0 = 1.0f / l0, inv1 = 1.0f / l1;
#pragma unroll
        for (int nt = 0; nt < 16; ++nt) {
            int r = row_base + g;
            int c = nt * 8 + t4 * 2;
            out[(size_t)r * DH + c]           = acc[nt][0] * inv0;
            out[(size_t)r * DH + c + 1]       = acc[nt][1] * inv0;
            out[(size_t)(r + 8) * DH + c]     = acc[nt][2] * inv1;
            out[(size_t)(r + 8) * DH + c + 1] = acc[nt][3] * inv1;
        }
    } else {
        const int pslot = qt * MAXC + ch;
        float* Op = g_Opart + (size_t)pslot * 64 * DH;
        const int lr0 = warp * 16 + g, lr1 = lr0 + 8;
#pragma unroll
        for (int nt = 0; nt < 16; ++nt) {
            int c = nt * 8 + t4 * 2;
            Op[(size_t)lr0 * DH + c]     = acc[nt][0];
            Op[(size_t)lr0 * DH + c + 1] = acc[nt][1];
            Op[(size_t)lr1 * DH + c]     = acc[nt][2];
            Op[(size_t)lr1 * DH + c + 1] = acc[nt][3];
        }
        if (t4 == 0) {
            g_mpart[pslot * 64 + lr0] = m0r;
            g_lpart[pslot * 64 + lr0] = l0;
            g_mpart[pslot * 64 + lr1] = m1r;
            g_lpart[pslot * 64 + lr1] = l1;
        }
    }
}

// ---------------------------------------------------------------------------
// Combine v2: rows 512..4095; 8 rows per 256-thr block, 32 thr/row,
// float4 Opart loads (4x MLP vs v1). grid = 448.
// ---------------------------------------------------------------------------
__global__ __launch_bounds__(256)
void combine_kernel(float* __restrict__ out) {
    const int lrow = threadIdx.x >> 5;         // 0..7
    const int c4   = (threadIdx.x & 31) * 4;   // column group
    const int row  = 512 + blockIdx.x * 8 + lrow;
    const int qt   = row >> 6;
    const int nc   = (qt >> 3) + 1;
    const int lr   = row & 63;

    float M = -1e30f;
#pragma unroll 4
    for (int c = 0; c < nc; ++c)
        M = fmaxf(M, g_mpart[(qt * MAXC + c) * 64 + lr]);

    float l = 0.f;
    float ox = 0.f, oy = 0.f, oz = 0.f, ow = 0.f;
#pragma unroll 4
    for (int c = 0; c < nc; ++c) {
        int pslot = qt * MAXC + c;
        float a = ex2(g_mpart[pslot * 64 + lr] - M);
        l += a * g_lpart[pslot * 64 + lr];
        float4 v = *(const float4*)&g_Opart[((size_t)pslot * 64 + lr) * DH + c4];
        ox += a * v.x; oy += a * v.y; oz += a * v.z; ow += a * v.w;
    }
    float inv = 1.0f / l;
    float4 o = { ox * inv, oy * inv, oz * inv, ow * inv };
    *(float4*)&out[(size_t)row * DH + c4] = o;
}

// ---------------------------------------------------------------------------

extern "C" void kernel_launch(void* const* d_in, const int* in_sizes, int n_in,
                              void* d_out, int out_size) {
    (void)in_sizes; (void)n_in; (void)out_size;
    const float* xq = (const float*)d_in[0];
    const float* xk = (const float*)d_in[1];
    const float* xv = (const float*)d_in[2];
    const float* wq = (const float*)d_in[3];
    const float* bq = (const float*)d_in[4];
    const float* wk = (const float*)d_in[5];
    const float* bk = (const float*)d_in[6];
    const float* wv = (const float*)d_in[7];
    const float* bv = (const float*)d_in[8];
    float* out = (float*)d_out;

    cudaFuncSetAttribute(proj_kernel, cudaFuncAttributeMaxDynamicSharedMemorySize, PJ_SMEM);

    prep_w<<<768, 256>>>(wq, wk, wv);
    proj_kernel<<<dim3(SEQ / 64, 3), 128, PJ_SMEM>>>(xq, xk, xv, bq, bk, bv);
    attn_kernel<<<dim3(SEQ / BM, MAXC), 128>>>(out);
    combine_kernel<<<(SEQ - 512) / 8, 256>>>(out);
}